// round 7
// baseline (speedup 1.0000x reference)
#include <cuda_runtime.h>
#include <cuda_bf16.h>
#include <stdint.h>

#define Bb 4
#define Nn 2048
#define Cc 1024
#define Hh 16
#define Dh 64
#define KK 1024

// Scratch (device globals)
__device__ float g_q[Bb * Hh * Nn * Dh];
__device__ float g_k[Bb * Hh * Nn * Dh];
__device__ float g_v[Bb * Hh * Nn * Dh];
__device__ float g_ao[Bb * Nn * Cc];
__device__ __nv_bfloat16 g_xhi[Bb * Nn * Cc];
__device__ __nv_bfloat16 g_xlo[Bb * Nn * Cc];
__device__ __nv_bfloat16 g_aohi[Bb * Nn * Cc];
__device__ __nv_bfloat16 g_aolo[Bb * Nn * Cc];
__device__ __nv_bfloat16 g_wqt_hi[3 * Cc * Cc];   // [3072][1024] K-major
__device__ __nv_bfloat16 g_wqt_lo[3 * Cc * Cc];
__device__ __nv_bfloat16 g_wpt_hi[Cc * Cc];       // [1024][1024] K-major
__device__ __nv_bfloat16 g_wpt_lo[Cc * Cc];

// ---------------- helpers ----------------
__device__ __forceinline__ unsigned long long ffma2(unsigned long long a,
                                                    unsigned long long b,
                                                    unsigned long long c) {
    unsigned long long d;
    asm("fma.rn.f32x2 %0, %1, %2, %3;" : "=l"(d) : "l"(a), "l"(b), "l"(c));
    return d;
}
__device__ __forceinline__ unsigned long long mul2(unsigned long long a,
                                                   unsigned long long b) {
    unsigned long long d;
    asm("mul.rn.f32x2 %0, %1, %2;" : "=l"(d) : "l"(a), "l"(b));
    return d;
}
__device__ __forceinline__ unsigned long long dup2(float x) {
    unsigned xi = __float_as_uint(x);
    unsigned long long d;
    asm("mov.b64 %0, {%1, %1};" : "=l"(d) : "r"(xi));
    return d;
}
__device__ __forceinline__ float2 unpk2(unsigned long long v) {
    unsigned lo, hi;
    asm("mov.b64 {%0, %1}, %2;" : "=r"(lo), "=r"(hi) : "l"(v));
    return make_float2(__uint_as_float(lo), __uint_as_float(hi));
}
__device__ __forceinline__ void cpa16(void* smem_ptr, const void* gptr) {
    unsigned sa = (unsigned)__cvta_generic_to_shared(smem_ptr);
    asm volatile("cp.async.cg.shared.global [%0], [%1], 16;" :: "r"(sa), "l"(gptr));
}
__device__ __forceinline__ void cpa16s(uint32_t sa, const void* gptr) {
    asm volatile("cp.async.cg.shared.global [%0], [%1], 16;" :: "r"(sa), "l"(gptr));
}
__device__ __forceinline__ void cpa_commit() {
    asm volatile("cp.async.commit_group;" ::: "memory");
}
__device__ __forceinline__ void cpa_wait0() {
    asm volatile("cp.async.wait_group 0;" ::: "memory");
}
__device__ __forceinline__ void cpa_wait1() {
    asm volatile("cp.async.wait_group 1;" ::: "memory");
}
__device__ __forceinline__ uint32_t s2u(const void* p) {
    uint32_t a;
    asm("{ .reg .u64 t; cvta.to.shared.u64 t, %1; cvt.u32.u64 %0, t; }"
        : "=r"(a) : "l"(p));
    return a;
}

#define LDSM4(r, addr) \
    asm volatile("ldmatrix.sync.aligned.m8n8.x4.shared.b16 {%0,%1,%2,%3}, [%4];" \
        : "=r"((r)[0]), "=r"((r)[1]), "=r"((r)[2]), "=r"((r)[3]) : "r"(addr))

#define MMA_BF16(d, a, b) \
    asm volatile("mma.sync.aligned.m16n8k16.row.col.f32.bf16.bf16.f32 " \
        "{%0,%1,%2,%3}, {%4,%5,%6,%7}, {%8,%9}, {%0,%1,%2,%3};" \
        : "+f"((d)[0]), "+f"((d)[1]), "+f"((d)[2]), "+f"((d)[3]) \
        : "r"((a)[0]), "r"((a)[1]), "r"((a)[2]), "r"((a)[3]), \
          "r"((b)[0]), "r"((b)[1]))

// ---------------------------------------------------------------------------
// Conversion kernels
// ---------------------------------------------------------------------------
struct bh4 { __nv_bfloat16 a, b, c, d; };

__global__ void split_bf16(const float4* __restrict__ src,
                           __nv_bfloat16* __restrict__ hi,
                           __nv_bfloat16* __restrict__ lo) {
    int i = blockIdx.x * 256 + threadIdx.x;
    float4 v = src[i];
    __nv_bfloat16 hx = __float2bfloat16(v.x);
    __nv_bfloat16 hy = __float2bfloat16(v.y);
    __nv_bfloat16 hz = __float2bfloat16(v.z);
    __nv_bfloat16 hw = __float2bfloat16(v.w);
    bh4 h = {hx, hy, hz, hw};
    bh4 l = {__float2bfloat16(v.x - __bfloat162float(hx)),
             __float2bfloat16(v.y - __bfloat162float(hy)),
             __float2bfloat16(v.z - __bfloat162float(hz)),
             __float2bfloat16(v.w - __bfloat162float(hw))};
    *(bh4*)(hi + 4 * i) = h;
    *(bh4*)(lo + 4 * i) = l;
}

// W[K][N] row-major -> Wt[N][K] bf16 hi/lo
__global__ void transpose_split(const float* __restrict__ W,
                                __nv_bfloat16* __restrict__ hi,
                                __nv_bfloat16* __restrict__ lo,
                                int K, int N) {
    __shared__ float t[32][33];
    const int n0 = blockIdx.x * 32, k0 = blockIdx.y * 32;
    const int tx = threadIdx.x, ty = threadIdx.y;
#pragma unroll
    for (int i = 0; i < 4; i++)
        t[ty + 8 * i][tx] = W[(k0 + ty + 8 * i) * N + n0 + tx];
    __syncthreads();
#pragma unroll
    for (int i = 0; i < 4; i++) {
        float v = t[tx][ty + 8 * i];
        __nv_bfloat16 h = __float2bfloat16(v);
        __nv_bfloat16 l = __float2bfloat16(v - __bfloat162float(h));
        int o = (n0 + ty + 8 * i) * K + k0 + tx;
        hi[o] = h;
        lo[o] = l;
    }
}

// ---------------------------------------------------------------------------
// mma.sync bf16 3-term GEMM: C = Ahi*Bhi + Ahi*Blo + Alo*Bhi (+bias)
// A: [M][1024] K-major bf16, B: [Ncols][1024] K-major bf16 (pre-transposed).
// CTA: 128x128 tile, 8 warps (4 M x 2 N), warp tile 32x64.
// K chunks of 32, 2-stage cp.async double buffer.
// ---------------------------------------------------------------------------
#define CH 32
#define PITB 80                    // smem row pitch in bytes (40 bf16)
#define TILE_B (128 * PITB)        // 10240
#define STAGE_B (4 * TILE_B)       // 40960
#define GEMM_SMEM (2 * STAGE_B)    // 81920

template <int EPI>
__global__ __launch_bounds__(256, 1) void mma_gemm(
    const __nv_bfloat16* __restrict__ Ahi, const __nv_bfloat16* __restrict__ Alo,
    const __nv_bfloat16* __restrict__ Bhi, const __nv_bfloat16* __restrict__ Blo,
    const float* __restrict__ bias, float* __restrict__ Cout, int Ncols)
{
    extern __shared__ __align__(128) char smem[];
    const uint32_t sb = s2u(smem);
    const int tid = threadIdx.x;
    const int wid = tid >> 5, lane = tid & 31;
    const int warpM = wid & 3, warpN = wid >> 2;
    const int rowBase = blockIdx.y * 128;
    const int colBase = blockIdx.x * 128;

    const __nv_bfloat16* Ah = Ahi + rowBase * KK;
    const __nv_bfloat16* Al = Alo + rowBase * KK;
    const __nv_bfloat16* Bh = Bhi + colBase * KK;
    const __nv_bfloat16* Bl = Blo + colBase * KK;

    float acc[2][8][4];
#pragma unroll
    for (int i = 0; i < 2; i++)
#pragma unroll
        for (int j = 0; j < 8; j++)
#pragma unroll
            for (int q = 0; q < 4; q++) acc[i][j][q] = 0.f;

    // ldmatrix base offsets (bytes) within a tile
    const uint32_t aOff =
        (uint32_t)((warpM * 32 + (lane & 15)) * PITB + (lane >> 4) * 16);
    const uint32_t bOff =
        (uint32_t)((warpN * 64 + ((lane >> 4) << 3) + (lane & 7)) * PITB +
                   ((lane >> 3) & 1) * 16);

    // global load mapping: 512 x 16B per tile; idx -> (row, quarter)
    const int r0 = tid >> 2, q0 = (tid & 3);
    const int r1 = (tid + 256) >> 2, q1 = ((tid + 256) & 3);

#define LOADC(c)                                                               \
    {                                                                          \
        const uint32_t st_ = sb + ((c) & 1) * STAGE_B;                         \
        const int k0_ = (c) * CH;                                              \
        {                                                                      \
            const uint32_t doff = (uint32_t)(r0 * PITB + q0 * 16);             \
            const int gs = r0 * KK + k0_ + q0 * 8;                             \
            cpa16s(st_ + doff, Ah + gs);                                       \
            cpa16s(st_ + TILE_B + doff, Al + gs);                              \
            cpa16s(st_ + 2 * TILE_B + doff, Bh + gs);                          \
            cpa16s(st_ + 3 * TILE_B + doff, Bl + gs);                          \
        }                                                                      \
        {                                                                      \
            const uint32_t doff = (uint32_t)(r1 * PITB + q1 * 16);             \
            const int gs = r1 * KK + k0_ + q1 * 8;                             \
            cpa16s(st_ + doff, Ah + gs);                                       \
            cpa16s(st_ + TILE_B + doff, Al + gs);                              \
            cpa16s(st_ + 2 * TILE_B + doff, Bh + gs);                          \
            cpa16s(st_ + 3 * TILE_B + doff, Bl + gs);                          \
        }                                                                      \
        cpa_commit();                                                          \
    }

    LOADC(0);

    for (int c = 0; c < KK / CH; c++) {
        if (c + 1 < KK / CH) {
            LOADC(c + 1);
            cpa_wait1();
        } else {
            cpa_wait0();
        }
        __syncthreads();

        const uint32_t st = sb + (c & 1) * STAGE_B;
#pragma unroll
        for (int ks = 0; ks < 2; ks++) {
            uint32_t ah[2][4], al[2][4];
#pragma unroll
            for (int mt = 0; mt < 2; mt++) {
                const uint32_t addr = st + aOff + mt * (16 * PITB) + ks * 32;
                LDSM4(ah[mt], addr);
                LDSM4(al[mt], addr + TILE_B);
            }
            uint32_t bh[4][4], bl[4][4];
#pragma unroll
            for (int nt = 0; nt < 4; nt++) {
                const uint32_t addr =
                    st + 2 * TILE_B + bOff + nt * (16 * PITB) + ks * 32;
                LDSM4(bh[nt], addr);
                LDSM4(bl[nt], addr + TILE_B);
            }
#pragma unroll
            for (int mt = 0; mt < 2; mt++)
#pragma unroll
                for (int nt = 0; nt < 4; nt++)
#pragma unroll
                    for (int sub = 0; sub < 2; sub++) {
                        const int n8 = nt * 2 + sub;
                        MMA_BF16(acc[mt][n8], ah[mt], (&bh[nt][sub * 2]));
                        MMA_BF16(acc[mt][n8], ah[mt], (&bl[nt][sub * 2]));
                        MMA_BF16(acc[mt][n8], al[mt], (&bh[nt][sub * 2]));
                    }
        }
        __syncthreads();
    }
#undef LOADC

    // Epilogue: per (mt, n8): rows rowT, rowT+8; cols col0, col0+1.
#pragma unroll
    for (int mt = 0; mt < 2; mt++) {
        const int rowT = rowBase + warpM * 32 + mt * 16 + (lane >> 2);
#pragma unroll
        for (int n8 = 0; n8 < 8; n8++) {
            const int col0 = colBase + warpN * 64 + n8 * 8 + (lane & 3) * 2;
            const float2 b2 = *(const float2*)&bias[col0];
            float2 vlo = make_float2(acc[mt][n8][0] + b2.x, acc[mt][n8][1] + b2.y);
            float2 vhi = make_float2(acc[mt][n8][2] + b2.x, acc[mt][n8][3] + b2.y);
            if (EPI == 0) {
                const int which = col0 >> 10;
                const int hh = (col0 & 1023) >> 6;
                const int dd = col0 & 63;
                float* base = (which == 0) ? g_q : (which == 1) ? g_k : g_v;
                const int bb = rowT >> 11;
                const int nn = rowT & 2047;
                *(float2*)&base[(((bb * Hh + hh) * Nn + nn) << 6) + dd] = vlo;
                const int rw2 = rowT + 8;
                const int bb2 = rw2 >> 11;
                const int nn2 = rw2 & 2047;
                *(float2*)&base[(((bb2 * Hh + hh) * Nn + nn2) << 6) + dd] = vhi;
            } else {
                *(float2*)&Cout[rowT * Ncols + col0] = vlo;
                *(float2*)&Cout[(rowT + 8) * Ncols + col0] = vhi;
            }
        }
    }
}

// ---------------------------------------------------------------------------
// Flash attention (fp32, identical to round-2 passing version)
// ---------------------------------------------------------------------------
#define QP 132
#define VP 68
#define OFF_QS 0
#define OFF_KS (64 * QP)
#define OFF_VS (OFF_KS + 2 * 8 * QP)
#define OFF_PS (OFF_VS + 128 * VP)
#define OFF_AR (OFF_PS + 128 * QP)
#define OFF_LR (OFF_AR + 128)
#define OFF_MK (OFF_LR + 128)
#define ATTN_SMEM_FLOATS (OFF_MK + 512)
#define ATTN_SMEM_BYTES (ATTN_SMEM_FLOATS * 4)

__global__ __launch_bounds__(256, 1) void attn_kernel(const uint8_t* __restrict__ mask)
{
    extern __shared__ float sm[];
    float* Qs = sm + OFF_QS;
    float* Ks = sm + OFF_KS;
    float* Vs = sm + OFF_VS;
    float* Ps = sm + OFF_PS;
    float* a_row = sm + OFF_AR;
    float* l_row = sm + OFF_LR;
    uint8_t* maskSm = (uint8_t*)(sm + OFF_MK);

    const int tid = threadIdx.x;
    const int tx = tid & 15;
    const int ty = tid >> 4;
    const int qb = blockIdx.x;
    const int h = blockIdx.y;
    const int b = blockIdx.z;

    const float* qp = g_q + ((b * Hh + h) * Nn + qb * 128) * Dh;
    const float* kb = g_k + ((b * Hh + h) * Nn) * Dh;
    const float* vb = g_v + ((b * Hh + h) * Nn) * Dh;

    const int g = tid >> 7;
    const int pt = tid & 127;
    const int ry = pt >> 3;
    const int rx = pt & 7;

    ((unsigned long long*)maskSm)[tid] =
        ((const unsigned long long*)(mask + b * Nn))[tid];

#pragma unroll
    for (int it = 0; it < 8; it++) {
        int idx = tid + it * 256;
        int q = idx >> 4;
        int d4 = (idx & 15) << 2;
        float4 v = *(const float4*)(qp + q * Dh + d4);
        Qs[(d4 + 0) * QP + q] = v.x * 0.125f;
        Qs[(d4 + 1) * QP + q] = v.y * 0.125f;
        Qs[(d4 + 2) * QP + q] = v.z * 0.125f;
        Qs[(d4 + 3) * QP + q] = v.w * 0.125f;
    }

    float m_r[8], l_r[8];
#pragma unroll
    for (int i = 0; i < 8; i++) { m_r[i] = -1e30f; l_r[i] = 0.f; }
    unsigned long long o2[8][4];
#pragma unroll
    for (int i = 0; i < 8; i++)
#pragma unroll
        for (int j = 0; j < 4; j++) o2[i][j] = 0ULL;

    const int akey = tid >> 1;
    const int ad4 = (tid & 1) << 2;

    for (int kt = 0; kt < Nn / 128; kt++) {
        __syncthreads();
        const float* kp = kb + kt * 128 * Dh;
        const float* vp = vb + kt * 128 * Dh;

#pragma unroll
        for (int it = 0; it < 8; it++) {
            int idx = tid + it * 256;
            int key = idx >> 4;
            int d4 = (idx & 15) << 2;
            cpa16(&Vs[key * VP + d4], vp + key * Dh + d4);
        }
        cpa_commit();

        unsigned long long s2[8][4];
#pragma unroll
        for (int i = 0; i < 8; i++)
#pragma unroll
            for (int j = 0; j < 4; j++) s2[i][j] = 0ULL;

        {
            float4 k0 = *(const float4*)(kp + akey * Dh + ad4);
            float* kd = Ks;
            kd[(ad4 + 0) * QP + akey] = k0.x;
            kd[(ad4 + 1) * QP + akey] = k0.y;
            kd[(ad4 + 2) * QP + akey] = k0.z;
            kd[(ad4 + 3) * QP + akey] = k0.w;
        }
        __syncthreads();

        for (int c = 0; c < 8; c++) {
            float4 knext;
            if (c < 7)
                knext = *(const float4*)(kp + akey * Dh + (c + 1) * 8 + ad4);
            const float* kbuf = Ks + (c & 1) * (8 * QP);
#pragma unroll
            for (int dd = 0; dd < 8; dd++) {
                const float* qrow = Qs + (c * 8 + dd) * QP;
                const float* krow = kbuf + dd * QP;
                float4 a0 = *(const float4*)(qrow + ty * 4);
                float4 a1 = *(const float4*)(qrow + 64 + ty * 4);
                ulonglong2 b0 = *(const ulonglong2*)(krow + tx * 4);
                ulonglong2 b1 = *(const ulonglong2*)(krow + 64 + tx * 4);
                unsigned long long br[4] = {b0.x, b0.y, b1.x, b1.y};
                float ar[8] = {a0.x, a0.y, a0.z, a0.w, a1.x, a1.y, a1.z, a1.w};
#pragma unroll
                for (int i = 0; i < 8; i++) {
                    unsigned long long ad = dup2(ar[i]);
#pragma unroll
                    for (int j = 0; j < 4; j++)
                        s2[i][j] = ffma2(ad, br[j], s2[i][j]);
                }
            }
            if (c < 7) {
                float* kd = Ks + ((c + 1) & 1) * (8 * QP);
                kd[(ad4 + 0) * QP + akey] = knext.x;
                kd[(ad4 + 1) * QP + akey] = knext.y;
                kd[(ad4 + 2) * QP + akey] = knext.z;
                kd[(ad4 + 3) * QP + akey] = knext.w;
                __syncthreads();
            }
        }

        cpa_wait0();

        const uint8_t* mrow = maskSm + kt * 128;
        float alpha_v[8];
#pragma unroll
        for (int ih = 0; ih < 2; ih++) {
            float pv4[4][8];
#pragma unroll
            for (int ii = 0; ii < 4; ii++) {
                const int i = ih * 4 + ii;
                float v[8];
#pragma unroll
                for (int j2 = 0; j2 < 4; j2++) {
                    float2 u = unpk2(s2[i][j2]);
                    v[j2 * 2] = u.x;
                    v[j2 * 2 + 1] = u.y;
                }
#pragma unroll
                for (int j = 0; j < 8; j++) {
                    int key = (j < 4) ? tx * 4 + j : 64 + tx * 4 + (j - 4);
                    if (mrow[key]) v[j] = -1e30f;
                }
                float tm = v[0];
#pragma unroll
                for (int j = 1; j < 8; j++) tm = fmaxf(tm, v[j]);
                tm = fmaxf(tm, __shfl_xor_sync(0xffffffffu, tm, 1));
                tm = fmaxf(tm, __shfl_xor_sync(0xffffffffu, tm, 2));
                tm = fmaxf(tm, __shfl_xor_sync(0xffffffffu, tm, 4));
                tm = fmaxf(tm, __shfl_xor_sync(0xffffffffu, tm, 8));
                const float mn = fmaxf(m_r[i], tm);
                float s = 0.f;
#pragma unroll
                for (int j = 0; j < 8; j++) {
                    float p = __expf(v[j] - mn);
                    pv4[ii][j] = p;
                    s += p;
                }
                s += __shfl_xor_sync(0xffffffffu, s, 1);
                s += __shfl_xor_sync(0xffffffffu, s, 2);
                s += __shfl_xor_sync(0xffffffffu, s, 4);
                s += __shfl_xor_sync(0xffffffffu, s, 8);
                const float al = __expf(m_r[i] - mn);
                alpha_v[i] = al;
                l_r[i] = al * l_r[i] + s;
                m_r[i] = mn;
            }
#pragma unroll
            for (int j = 0; j < 8; j++) {
                int key = (j < 4) ? tx * 4 + j : 64 + tx * 4 + (j - 4);
                float4 o4 = make_float4(pv4[0][j], pv4[1][j], pv4[2][j], pv4[3][j]);
                *(float4*)&Ps[key * QP + ih * 64 + ty * 4] = o4;
            }
        }
        if (tx == 0) {
#pragma unroll
            for (int i = 0; i < 8; i++) {
                int r = (i < 4) ? ty * 4 + i : 64 + ty * 4 + (i - 4);
                a_row[r] = alpha_v[i];
                if (kt == Nn / 128 - 1) l_row[r] = l_r[i];
            }
        }
        __syncthreads();

        float alph[8];
#pragma unroll
        for (int i = 0; i < 8; i++) {
            int r = (i < 4) ? ry * 4 + i : 64 + ry * 4 + (i - 4);
            alph[i] = a_row[r];
        }
#pragma unroll
        for (int i = 0; i < 8; i++) {
            unsigned long long ad = dup2(alph[i]);
#pragma unroll
            for (int j = 0; j < 4; j++) o2[i][j] = mul2(ad, o2[i][j]);
        }
#pragma unroll 8
        for (int kk = 0; kk < 64; kk++) {
            const int key = g * 64 + kk;
            float4 p0 = *(const float4*)&Ps[key * QP + ry * 4];
            float4 p1 = *(const float4*)&Ps[key * QP + 64 + ry * 4];
            ulonglong2 v0 = *(const ulonglong2*)&Vs[key * VP + rx * 8];
            ulonglong2 v1 = *(const ulonglong2*)&Vs[key * VP + rx * 8 + 4];
            unsigned long long vr[4] = {v0.x, v0.y, v1.x, v1.y};
            float pr[8] = {p0.x, p0.y, p0.z, p0.w, p1.x, p1.y, p1.z, p1.w};
#pragma unroll
            for (int i = 0; i < 8; i++) {
                unsigned long long pd = dup2(pr[i]);
#pragma unroll
                for (int j = 0; j < 4; j++)
                    o2[i][j] = ffma2(pd, vr[j], o2[i][j]);
            }
        }
    }

    __syncthreads();
    if (g == 1) {
#pragma unroll
        for (int i = 0; i < 8; i++) {
            int r = (i < 4) ? ry * 4 + i : 64 + ry * 4 + (i - 4);
            float2 u0 = unpk2(o2[i][0]);
            float2 u1 = unpk2(o2[i][1]);
            float2 u2 = unpk2(o2[i][2]);
            float2 u3 = unpk2(o2[i][3]);
            *(float4*)&Ps[r * VP + rx * 8] = make_float4(u0.x, u0.y, u1.x, u1.y);
            *(float4*)&Ps[r * VP + rx * 8 + 4] = make_float4(u2.x, u2.y, u3.x, u3.y);
        }
    }
    __syncthreads();
    if (g == 0) {
#pragma unroll
        for (int i = 0; i < 8; i++) {
            int r = (i < 4) ? ry * 4 + i : 64 + ry * 4 + (i - 4);
            float invl = 1.f / l_row[r];
            float4 q0 = *(const float4*)&Ps[r * VP + rx * 8];
            float4 q1 = *(const float4*)&Ps[r * VP + rx * 8 + 4];
            float2 u0 = unpk2(o2[i][0]);
            float2 u1 = unpk2(o2[i][1]);
            float2 u2 = unpk2(o2[i][2]);
            float2 u3 = unpk2(o2[i][3]);
            float* dst = g_ao + (b * Nn + qb * 128 + r) * Cc + h * Dh + rx * 8;
            float4 w0, w1;
            w0.x = (u0.x + q0.x) * invl;
            w0.y = (u0.y + q0.y) * invl;
            w0.z = (u1.x + q0.z) * invl;
            w0.w = (u1.y + q0.w) * invl;
            w1.x = (u2.x + q1.x) * invl;
            w1.y = (u2.y + q1.y) * invl;
            w1.z = (u3.x + q1.z) * invl;
            w1.w = (u3.y + q1.w) * invl;
            *(float4*)dst = w0;
            *(float4*)(dst + 4) = w1;
        }
    }
}

// ---------------------------------------------------------------------------
extern "C" void kernel_launch(void* const* d_in, const int* in_sizes, int n_in,
                              void* d_out, int out_size)
{
    (void)in_sizes; (void)n_in; (void)out_size;
    const float* x      = (const float*)d_in[0];
    const uint8_t* mask = (const uint8_t*)d_in[1];
    const float* Wqkv   = (const float*)d_in[2];
    const float* bqkv   = (const float*)d_in[3];
    const float* Wproj  = (const float*)d_in[4];
    const float* bproj  = (const float*)d_in[5];
    float* out = (float*)d_out;

    __nv_bfloat16 *xhi, *xlo, *aohi, *aolo, *wqh, *wql, *wph, *wpl;
    float *gao;
    cudaGetSymbolAddress((void**)&xhi, g_xhi);
    cudaGetSymbolAddress((void**)&xlo, g_xlo);
    cudaGetSymbolAddress((void**)&aohi, g_aohi);
    cudaGetSymbolAddress((void**)&aolo, g_aolo);
    cudaGetSymbolAddress((void**)&wqh, g_wqt_hi);
    cudaGetSymbolAddress((void**)&wql, g_wqt_lo);
    cudaGetSymbolAddress((void**)&wph, g_wpt_hi);
    cudaGetSymbolAddress((void**)&wpl, g_wpt_lo);
    cudaGetSymbolAddress((void**)&gao, g_ao);

    const int NE = Bb * Nn * Cc;

    // 1) input & weight conversion
    split_bf16<<<NE / 4 / 256, 256>>>((const float4*)x, xhi, xlo);
    transpose_split<<<dim3(3 * Cc / 32, Cc / 32), dim3(32, 8)>>>(
        Wqkv, wqh, wql, Cc, 3 * Cc);
    transpose_split<<<dim3(Cc / 32, Cc / 32), dim3(32, 8)>>>(
        Wproj, wph, wpl, Cc, Cc);

    // 2) QKV projection (mma.sync bf16, 3-term)
    cudaFuncSetAttribute(mma_gemm<0>, cudaFuncAttributeMaxDynamicSharedMemorySize,
                         GEMM_SMEM);
    mma_gemm<0><<<dim3(3 * Cc / 128, Bb * Nn / 128), 256, GEMM_SMEM>>>(
        xhi, xlo, wqh, wql, bqkv, nullptr, 3 * Cc);

    // 3) Flash attention (fp32)
    cudaFuncSetAttribute(attn_kernel, cudaFuncAttributeMaxDynamicSharedMemorySize,
                         ATTN_SMEM_BYTES);
    attn_kernel<<<dim3(Nn / 128, Hh, Bb), 256, ATTN_SMEM_BYTES>>>(mask);

    // 4) attention-output conversion + output projection
    split_bf16<<<NE / 4 / 256, 256>>>((const float4*)gao, aohi, aolo);
    cudaFuncSetAttribute(mma_gemm<1>, cudaFuncAttributeMaxDynamicSharedMemorySize,
                         GEMM_SMEM);
    mma_gemm<1><<<dim3(Cc / 128, Bb * Nn / 128), 256, GEMM_SMEM>>>(
        aohi, aolo, wph, wpl, bproj, out, Cc);
}

// round 9
// speedup vs baseline: 1.7782x; 1.7782x over previous
#include <cuda_runtime.h>
#include <cuda_bf16.h>
#include <stdint.h>

#define Bb 4
#define Nn 2048
#define Cc 1024
#define Hh 16
#define Dh 64
#define KK 1024
typedef __nv_bfloat16 bf;

__device__ float g_ao[Bb * Nn * Cc];
__device__ bf g_xhi[Bb * Nn * Cc];
__device__ bf g_xlo[Bb * Nn * Cc];
__device__ bf g_aohi[Bb * Nn * Cc];
__device__ bf g_aolo[Bb * Nn * Cc];
__device__ bf g_qhi[Bb * Hh * Nn * Dh];
__device__ bf g_qlo[Bb * Hh * Nn * Dh];
__device__ bf g_khi[Bb * Hh * Nn * Dh];
__device__ bf g_klo[Bb * Hh * Nn * Dh];
__device__ bf g_vhi[Bb * Hh * Nn * Dh];
__device__ bf g_vlo[Bb * Hh * Nn * Dh];
__device__ bf g_wqt_hi[3 * Cc * Cc];
__device__ bf g_wqt_lo[3 * Cc * Cc];
__device__ bf g_wpt_hi[Cc * Cc];
__device__ bf g_wpt_lo[Cc * Cc];

__device__ __forceinline__ void cpa16s(uint32_t sa, const void* g) {
    asm volatile("cp.async.cg.shared.global [%0], [%1], 16;" :: "r"(sa), "l"(g));
}
__device__ __forceinline__ void cpa_commit() {
    asm volatile("cp.async.commit_group;" ::: "memory");
}
#define CPA_WAIT(n) asm volatile("cp.async.wait_group %0;" :: "n"(n) : "memory")
__device__ __forceinline__ uint32_t s2u(const void* p) {
    uint32_t a;
    asm("{ .reg .u64 t; cvta.to.shared.u64 t, %1; cvt.u32.u64 %0, t; }" : "=r"(a) : "l"(p));
    return a;
}
__device__ __forceinline__ uint32_t cvt2(float hi, float lo) {
    uint32_t r;
    asm("cvt.rn.bf16x2.f32 %0, %1, %2;" : "=r"(r) : "f"(hi), "f"(lo));
    return r;
}
__device__ __forceinline__ uint32_t losplit(uint32_t hp, float v1, float v0) {
    float f0 = __uint_as_float(hp << 16);
    float f1 = __uint_as_float(hp & 0xffff0000u);
    return cvt2(v1 - f1, v0 - f0);
}
#define LDSM4(r, a) \
    asm volatile("ldmatrix.sync.aligned.m8n8.x4.shared.b16 {%0,%1,%2,%3}, [%4];" \
        : "=r"((r)[0]), "=r"((r)[1]), "=r"((r)[2]), "=r"((r)[3]) : "r"(a))
#define LDSM4T(r, a) \
    asm volatile("ldmatrix.sync.aligned.m8n8.x4.trans.shared.b16 {%0,%1,%2,%3}, [%4];" \
        : "=r"((r)[0]), "=r"((r)[1]), "=r"((r)[2]), "=r"((r)[3]) : "r"(a))
#define MMA(d, a, b) \
    asm volatile("mma.sync.aligned.m16n8k16.row.col.f32.bf16.bf16.f32 " \
        "{%0,%1,%2,%3}, {%4,%5,%6,%7}, {%8,%9}, {%0,%1,%2,%3};" \
        : "+f"((d)[0]), "+f"((d)[1]), "+f"((d)[2]), "+f"((d)[3]) \
        : "r"((a)[0]), "r"((a)[1]), "r"((a)[2]), "r"((a)[3]), "r"((b)[0]), "r"((b)[1]))

// -------------------- conversions --------------------
struct bh4 { bf a, b, c, d; };
__global__ void split_bf16(const float4* __restrict__ s, bf* __restrict__ hi,
                           bf* __restrict__ lo) {
    int i = blockIdx.x * 256 + threadIdx.x;
    float4 v = s[i];
    bf hx = __float2bfloat16(v.x), hy = __float2bfloat16(v.y);
    bf hz = __float2bfloat16(v.z), hw = __float2bfloat16(v.w);
    bh4 h = {hx, hy, hz, hw};
    bh4 l = {__float2bfloat16(v.x - __bfloat162float(hx)),
             __float2bfloat16(v.y - __bfloat162float(hy)),
             __float2bfloat16(v.z - __bfloat162float(hz)),
             __float2bfloat16(v.w - __bfloat162float(hw))};
    *(bh4*)(hi + 4 * i) = h;
    *(bh4*)(lo + 4 * i) = l;
}
__global__ void transpose_split(const float* __restrict__ W, bf* __restrict__ hi,
                                bf* __restrict__ lo, int K, int N) {
    __shared__ float t[32][33];
    const int n0 = blockIdx.x * 32, k0 = blockIdx.y * 32;
    const int tx = threadIdx.x, ty = threadIdx.y;
#pragma unroll
    for (int i = 0; i < 4; i++)
        t[ty + 8 * i][tx] = W[(k0 + ty + 8 * i) * N + n0 + tx];
    __syncthreads();
#pragma unroll
    for (int i = 0; i < 4; i++) {
        float v = t[tx][ty + 8 * i];
        bf h = __float2bfloat16(v);
        bf l = __float2bfloat16(v - __bfloat162float(h));
        int o = (n0 + ty + 8 * i) * K + k0 + tx;
        hi[o] = h; lo[o] = l;
    }
}

// -------------------- GEMM (4-stage) --------------------
#define CH 32
#define PITB 80
#define TILE_B (128 * PITB)
#define STAGE_B (4 * TILE_B)
#define GEMM_SMEM (4 * STAGE_B)

template <int EPI>
__global__ __launch_bounds__(256, 1) void mma_gemm(
    const bf* __restrict__ Ahi, const bf* __restrict__ Alo,
    const bf* __restrict__ Bhi, const bf* __restrict__ Blo,
    const float* __restrict__ bias, float* __restrict__ Cout, int Ncols)
{
    extern __shared__ __align__(128) char smem[];
    const uint32_t sb = s2u(smem);
    const int tid = threadIdx.x, wid = tid >> 5, lane = tid & 31;
    const int warpM = wid & 3, warpN = wid >> 2;
    const int rowBase = blockIdx.y * 128, colBase = blockIdx.x * 128;
    const bf* Ah = Ahi + rowBase * KK;
    const bf* Al = Alo + rowBase * KK;
    const bf* Bh = Bhi + colBase * KK;
    const bf* Bl = Blo + colBase * KK;

    float acc[2][8][4];
#pragma unroll
    for (int i = 0; i < 2; i++)
#pragma unroll
        for (int j = 0; j < 8; j++)
#pragma unroll
            for (int q = 0; q < 4; q++) acc[i][j][q] = 0.f;

    const uint32_t aOff = (uint32_t)((warpM * 32 + (lane & 15)) * PITB + (lane >> 4) * 16);
    const uint32_t bOff = (uint32_t)((warpN * 64 + ((lane >> 4) << 3) + (lane & 7)) * PITB +
                                     ((lane >> 3) & 1) * 16);
    const int r0 = tid >> 2, q0 = tid & 3;
    const int r1 = (tid + 256) >> 2, q1 = (tid + 256) & 3;

#define LOADC(c)                                                       \
    {                                                                  \
        const uint32_t st_ = sb + ((c) & 3) * STAGE_B;                 \
        const int k0_ = (c) * CH;                                      \
        const uint32_t d0 = (uint32_t)(r0 * PITB + q0 * 16);           \
        const int g0 = r0 * KK + k0_ + q0 * 8;                         \
        cpa16s(st_ + d0, Ah + g0);                                     \
        cpa16s(st_ + TILE_B + d0, Al + g0);                            \
        cpa16s(st_ + 2 * TILE_B + d0, Bh + g0);                        \
        cpa16s(st_ + 3 * TILE_B + d0, Bl + g0);                        \
        const uint32_t d1 = (uint32_t)(r1 * PITB + q1 * 16);           \
        const int g1 = r1 * KK + k0_ + q1 * 8;                         \
        cpa16s(st_ + d1, Ah + g1);                                     \
        cpa16s(st_ + TILE_B + d1, Al + g1);                            \
        cpa16s(st_ + 2 * TILE_B + d1, Bh + g1);                        \
        cpa16s(st_ + 3 * TILE_B + d1, Bl + g1);                        \
        cpa_commit();                                                  \
    }

    LOADC(0); LOADC(1); LOADC(2);
    const int NC = KK / CH;
    for (int c = 0; c < NC; c++) {
        if (c + 2 < NC) CPA_WAIT(2);
        else if (c + 1 < NC) CPA_WAIT(1);
        else CPA_WAIT(0);
        __syncthreads();
        if (c + 3 < NC) LOADC(c + 3);
        const uint32_t st = sb + (c & 3) * STAGE_B;
#pragma unroll
        for (int ks = 0; ks < 2; ks++) {
            uint32_t ah[2][4], al[2][4], bh[4][4], bl[4][4];
#pragma unroll
            for (int mt = 0; mt < 2; mt++) {
                const uint32_t a = st + aOff + mt * (16 * PITB) + ks * 32;
                LDSM4(ah[mt], a); LDSM4(al[mt], a + TILE_B);
            }
#pragma unroll
            for (int nt = 0; nt < 4; nt++) {
                const uint32_t a = st + 2 * TILE_B + bOff + nt * (16 * PITB) + ks * 32;
                LDSM4(bh[nt], a); LDSM4(bl[nt], a + TILE_B);
            }
#pragma unroll
            for (int mt = 0; mt < 2; mt++)
#pragma unroll
                for (int nt = 0; nt < 4; nt++)
#pragma unroll
                    for (int sub = 0; sub < 2; sub++) {
                        const int n8 = nt * 2 + sub;
                        MMA(acc[mt][n8], ah[mt], (&bh[nt][sub * 2]));
                        MMA(acc[mt][n8], ah[mt], (&bl[nt][sub * 2]));
                        MMA(acc[mt][n8], al[mt], (&bh[nt][sub * 2]));
                    }
        }
    }
#undef LOADC

#pragma unroll
    for (int mt = 0; mt < 2; mt++) {
        const int rowT = rowBase + warpM * 32 + mt * 16 + (lane >> 2);
#pragma unroll
        for (int n8 = 0; n8 < 8; n8++) {
            const int col0 = colBase + warpN * 64 + n8 * 8 + ((lane & 3) << 1);
            const float2 b2 = *(const float2*)&bias[col0];
            float v0 = acc[mt][n8][0] + b2.x, v1 = acc[mt][n8][1] + b2.y;
            float v2 = acc[mt][n8][2] + b2.x, v3 = acc[mt][n8][3] + b2.y;
            if (EPI == 0) {
                const int which = col0 >> 10;
                const int hh = (col0 & 1023) >> 6, dd = col0 & 63;
                if (which == 0) { v0 *= 0.125f; v1 *= 0.125f; v2 *= 0.125f; v3 *= 0.125f; }
                bf* dh = (which == 0) ? g_qhi : (which == 1) ? g_khi : g_vhi;
                bf* dl = (which == 0) ? g_qlo : (which == 1) ? g_klo : g_vlo;
                const int o1 = ((((rowT >> 11) * Hh + hh) * Nn + (rowT & 2047)) << 6) + dd;
                const int rw = rowT + 8;
                const int o2 = ((((rw >> 11) * Hh + hh) * Nn + (rw & 2047)) << 6) + dd;
                uint32_t h0 = cvt2(v1, v0), h1 = cvt2(v3, v2);
                *(uint32_t*)(dh + o1) = h0;
                *(uint32_t*)(dl + o1) = losplit(h0, v1, v0);
                *(uint32_t*)(dh + o2) = h1;
                *(uint32_t*)(dl + o2) = losplit(h1, v3, v2);
            } else {
                *(float2*)&Cout[rowT * Ncols + col0] = make_float2(v0, v1);
                *(float2*)&Cout[(rowT + 8) * Ncols + col0] = make_float2(v2, v3);
            }
        }
    }
}

// -------------------- attention (mma.sync bf16) --------------------
#define PIT 144
#define AQH 0
#define AQL 18432
#define AST 36864
#define ASTB 73728          // per-stage: KH,KL,VH,VL each 18432
#define AMB 184320
#define ATTN_SMEM (AMB + 1024)

__global__ __launch_bounds__(256, 1) void attn_mma(const uint8_t* __restrict__ mask)
{
    extern __shared__ __align__(128) char smc[];
    const uint32_t sb = s2u(smc);
    float* maskb = (float*)(smc + AMB);
    const int tid = threadIdx.x, wid = tid >> 5, lane = tid & 31;
    const int qblk = blockIdx.x, h = blockIdx.y, b = blockIdx.z;
    const int bh_ = (b * Hh + h) * Nn;
    const bf* qh = g_qhi + (bh_ + qblk * 128) * Dh;
    const bf* ql = g_qlo + (bh_ + qblk * 128) * Dh;
    const bf* kh = g_khi + bh_ * Dh;
    const bf* kl = g_klo + bh_ * Dh;
    const bf* vh = g_vhi + bh_ * Dh;
    const bf* vl = g_vlo + bh_ * Dh;
    const uint8_t* mrow = mask + b * Nn;

    // Q load: 128 rows x 64 bf16, hi+lo
#pragma unroll
    for (int it = 0; it < 4; it++) {
        int idx = tid + it * 256, r = idx >> 3, c = idx & 7;
        uint32_t off = (uint32_t)(r * PIT + c * 16);
        cpa16s(sb + AQH + off, qh + r * Dh + c * 8);
        cpa16s(sb + AQL + off, ql + r * Dh + c * 8);
    }
    cpa_commit();

#define LOADKV(kt)                                                          \
    {                                                                       \
        const uint32_t base = sb + AST + ((kt) & 1) * ASTB;                 \
        _Pragma("unroll")                                                   \
        for (int it = 0; it < 4; it++) {                                    \
            int idx = tid + it * 256, r = idx >> 3, c = idx & 7;            \
            uint32_t off = (uint32_t)(r * PIT + c * 16);                    \
            int gs = ((kt) * 128 + r) * Dh + c * 8;                         \
            cpa16s(base + off, kh + gs);                                    \
            cpa16s(base + 18432 + off, kl + gs);                            \
            cpa16s(base + 36864 + off, vh + gs);                            \
            cpa16s(base + 55296 + off, vl + gs);                            \
        }                                                                   \
        cpa_commit();                                                       \
        if (tid < 128)                                                      \
            maskb[((kt) & 1) * 128 + tid] = mrow[(kt) * 128 + tid] ? -1e30f : 0.f; \
    }

    LOADKV(0);

    float oacc[8][4];
#pragma unroll
    for (int j = 0; j < 8; j++)
#pragma unroll
        for (int q = 0; q < 4; q++) oacc[j][q] = 0.f;
    float m0 = -1e30f, m1 = -1e30f, l0 = 0.f, l1 = 0.f;

    const uint32_t aOffQ = sb + (uint32_t)((wid * 16 + (lane & 15)) * PIT + (lane >> 4) * 16);
    const uint32_t bOffK = (uint32_t)((((lane >> 4) << 3) + (lane & 7)) * PIT +
                                      ((lane >> 3) & 1) * 16);
    const uint32_t vOff = (uint32_t)(((lane & 7) + ((lane >> 3) & 1) * 8) * PIT +
                                     (lane >> 4) * 16);

    for (int kt = 0; kt < Nn / 128; kt++) {
        CPA_WAIT(0);
        __syncthreads();
        if (kt + 1 < Nn / 128) LOADKV(kt + 1);
        const uint32_t st = sb + AST + (kt & 1) * ASTB;

        float sacc[16][4];
#pragma unroll
        for (int j = 0; j < 16; j++)
#pragma unroll
            for (int q = 0; q < 4; q++) sacc[j][q] = 0.f;

#pragma unroll
        for (int kk = 0; kk < 4; kk++) {
            uint32_t qa[4], qb_[4];
            LDSM4(qa, aOffQ + kk * 32);
            LDSM4(qb_, aOffQ + 18432 + kk * 32);
#pragma unroll
            for (int nt = 0; nt < 8; nt++) {
                uint32_t kA = st + bOffK + (uint32_t)(nt * 16 * PIT) + kk * 32;
                uint32_t kbh[4], kbl[4];
                LDSM4(kbh, kA);
                LDSM4(kbl, kA + 18432);
#pragma unroll
                for (int sub = 0; sub < 2; sub++) {
                    const int j = nt * 2 + sub;
                    MMA(sacc[j], qa, (&kbh[sub * 2]));
                    MMA(sacc[j], qa, (&kbl[sub * 2]));
                    MMA(sacc[j], qb_, (&kbh[sub * 2]));
                }
            }
        }

        // softmax (warp-local; rows r=lane>>2 and r+8)
        float nm0 = m0, nm1 = m1;
        const float* mb = maskb + (kt & 1) * 128 + ((lane & 3) << 1);
#pragma unroll
        for (int j = 0; j < 16; j++) {
            float2 mv = *(const float2*)(mb + j * 8);
            sacc[j][0] += mv.x; sacc[j][1] += mv.y;
            sacc[j][2] += mv.x; sacc[j][3] += mv.y;
            nm0 = fmaxf(nm0, fmaxf(sacc[j][0], sacc[j][1]));
            nm1 = fmaxf(nm1, fmaxf(sacc[j][2], sacc[j][3]));
        }
        nm0 = fmaxf(nm0, __shfl_xor_sync(0xffffffffu, nm0, 1));
        nm0 = fmaxf(nm0, __shfl_xor_sync(0xffffffffu, nm0, 2));
        nm1 = fmaxf(nm1, __shfl_xor_sync(0xffffffffu, nm1, 1));
        nm1 = fmaxf(nm1, __shfl_xor_sync(0xffffffffu, nm1, 2));
        const float a0 = __expf(m0 - nm0), a1 = __expf(m1 - nm1);
        float s0 = 0.f, s1 = 0.f;
#pragma unroll
        for (int j = 0; j < 16; j++) {
            sacc[j][0] = __expf(sacc[j][0] - nm0);
            sacc[j][1] = __expf(sacc[j][1] - nm0);
            sacc[j][2] = __expf(sacc[j][2] - nm1);
            sacc[j][3] = __expf(sacc[j][3] - nm1);
            s0 += sacc[j][0] + sacc[j][1];
            s1 += sacc[j][2] + sacc[j][3];
        }
        s0 += __shfl_xor_sync(0xffffffffu, s0, 1);
        s0 += __shfl_xor_sync(0xffffffffu, s0, 2);
        s1 += __shfl_xor_sync(0xffffffffu, s1, 1);
        s1 += __shfl_xor_sync(0xffffffffu, s1, 2);
        l0 = a0 * l0 + s0; l1 = a1 * l1 + s1;
        m0 = nm0; m1 = nm1;
#pragma unroll
        for (int j = 0; j < 8; j++) {
            oacc[j][0] *= a0; oacc[j][1] *= a0;
            oacc[j][2] *= a1; oacc[j][3] *= a1;
        }

        // P*V (P repacked from S fragments, 3-term)
        const uint32_t vb = st + 36864;
#pragma unroll
        for (int kk2 = 0; kk2 < 8; kk2++) {
            const int f0 = kk2 * 2, f1 = f0 + 1;
            uint32_t ph[4], pl[4];
            ph[0] = cvt2(sacc[f0][1], sacc[f0][0]);
            ph[1] = cvt2(sacc[f0][3], sacc[f0][2]);
            ph[2] = cvt2(sacc[f1][1], sacc[f1][0]);
            ph[3] = cvt2(sacc[f1][3], sacc[f1][2]);
            pl[0] = losplit(ph[0], sacc[f0][1], sacc[f0][0]);
            pl[1] = losplit(ph[1], sacc[f0][3], sacc[f0][2]);
            pl[2] = losplit(ph[2], sacc[f1][1], sacc[f1][0]);
            pl[3] = losplit(ph[3], sacc[f1][3], sacc[f1][2]);
#pragma unroll
            for (int nt = 0; nt < 4; nt++) {
                const uint32_t va = vb + (uint32_t)(kk2 * 16 * PIT) + nt * 32 + vOff;
                uint32_t fh[4], fl[4];
                LDSM4T(fh, va);
                LDSM4T(fl, va + 18432);
#pragma unroll
                for (int sub = 0; sub < 2; sub++) {
                    const int n8 = nt * 2 + sub;
                    MMA(oacc[n8], ph, (&fh[sub * 2]));
                    MMA(oacc[n8], ph, (&fl[sub * 2]));
                    MMA(oacc[n8], pl, (&fh[sub * 2]));
                }
            }
        }
    }
#undef LOADKV

    const float i0 = 1.f / l0, i1 = 1.f / l1;
    const int q0 = qblk * 128 + wid * 16 + (lane >> 2);
    float* d0 = g_ao + (b * Nn + q0) * Cc + h * Dh;
    float* d1 = d0 + 8 * Cc;
#pragma unroll
    for (int n8 = 0; n8 < 8; n8++) {
        const int col = n8 * 8 + ((lane & 3) << 1);
        *(float2*)(d0 + col) = make_float2(oacc[n8][0] * i0, oacc[n8][1] * i0);
        *(float2*)(d1 + col) = make_float2(oacc[n8][2] * i1, oacc[n8][3] * i1);
    }
}

// ---------------------------------------------------------------------------
extern "C" void kernel_launch(void* const* d_in, const int* in_sizes, int n_in,
                              void* d_out, int out_size)
{
    (void)in_sizes; (void)n_in; (void)out_size;
    const float* x      = (const float*)d_in[0];
    const uint8_t* mask = (const uint8_t*)d_in[1];
    const float* Wqkv   = (const float*)d_in[2];
    const float* bqkv   = (const float*)d_in[3];
    const float* Wproj  = (const float*)d_in[4];
    const float* bproj  = (const float*)d_in[5];
    float* out = (float*)d_out;

    bf *xhi, *xlo, *aohi, *aolo, *wqh, *wql, *wph, *wpl;
    float* gao;
    cudaGetSymbolAddress((void**)&xhi, g_xhi);
    cudaGetSymbolAddress((void**)&xlo, g_xlo);
    cudaGetSymbolAddress((void**)&aohi, g_aohi);
    cudaGetSymbolAddress((void**)&aolo, g_aolo);
    cudaGetSymbolAddress((void**)&wqh, g_wqt_hi);
    cudaGetSymbolAddress((void**)&wql, g_wqt_lo);
    cudaGetSymbolAddress((void**)&wph, g_wpt_hi);
    cudaGetSymbolAddress((void**)&wpl, g_wpt_lo);
    cudaGetSymbolAddress((void**)&gao, g_ao);

    const int NE = Bb * Nn * Cc;
    split_bf16<<<NE / 4 / 256, 256>>>((const float4*)x, xhi, xlo);
    transpose_split<<<dim3(3 * Cc / 32, Cc / 32), dim3(32, 8)>>>(Wqkv, wqh, wql, Cc, 3 * Cc);
    transpose_split<<<dim3(Cc / 32, Cc / 32), dim3(32, 8)>>>(Wproj, wph, wpl, Cc, Cc);

    cudaFuncSetAttribute(mma_gemm<0>, cudaFuncAttributeMaxDynamicSharedMemorySize, GEMM_SMEM);
    mma_gemm<0><<<dim3(3 * Cc / 128, Bb * Nn / 128), 256, GEMM_SMEM>>>(
        xhi, xlo, wqh, wql, bqkv, nullptr, 3 * Cc);

    cudaFuncSetAttribute(attn_mma, cudaFuncAttributeMaxDynamicSharedMemorySize, ATTN_SMEM);
    attn_mma<<<dim3(Nn / 128, Hh, Bb), 256, ATTN_SMEM>>>(mask);

    split_bf16<<<NE / 4 / 256, 256>>>((const float4*)gao, aohi, aolo);
    cudaFuncSetAttribute(mma_gemm<1>, cudaFuncAttributeMaxDynamicSharedMemorySize, GEMM_SMEM);
    mma_gemm<1><<<dim3(Cc / 128, Bb * Nn / 128), 256, GEMM_SMEM>>>(
        aohi, aolo, wph, wpl, bproj, out, Cc);
}

// round 14
// speedup vs baseline: 1.8413x; 1.0355x over previous
#include <cuda_runtime.h>
#include <cuda_bf16.h>
#include <stdint.h>

#define Bb 4
#define Nn 2048
#define Cc 1024
#define Hh 16
#define Dh 64
#define KK 1024
typedef __nv_bfloat16 bf;

__device__ bf g_xhi[Bb * Nn * Cc];
__device__ bf g_xlo[Bb * Nn * Cc];
__device__ bf g_aohi[Bb * Nn * Cc];
__device__ bf g_aolo[Bb * Nn * Cc];
__device__ bf g_qhi[Bb * Hh * Nn * Dh];
__device__ bf g_qlo[Bb * Hh * Nn * Dh];
__device__ bf g_khi[Bb * Hh * Nn * Dh];
__device__ bf g_klo[Bb * Hh * Nn * Dh];
__device__ bf g_vhi[Bb * Hh * Nn * Dh];
__device__ bf g_vlo[Bb * Hh * Nn * Dh];
__device__ bf g_wqt_hi[3 * Cc * Cc];
__device__ bf g_wqt_lo[3 * Cc * Cc];
__device__ bf g_wpt_hi[Cc * Cc];
__device__ bf g_wpt_lo[Cc * Cc];

__device__ __forceinline__ void cpa16s(uint32_t sa, const void* g) {
    asm volatile("cp.async.cg.shared.global [%0], [%1], 16;" :: "r"(sa), "l"(g));
}
__device__ __forceinline__ void cpa_commit() {
    asm volatile("cp.async.commit_group;" ::: "memory");
}
#define CPA_WAIT(n) asm volatile("cp.async.wait_group %0;" :: "n"(n) : "memory")
__device__ __forceinline__ uint32_t s2u(const void* p) {
    uint32_t a;
    asm("{ .reg .u64 t; cvta.to.shared.u64 t, %1; cvt.u32.u64 %0, t; }" : "=r"(a) : "l"(p));
    return a;
}
__device__ __forceinline__ uint32_t cvt2(float hi, float lo) {
    uint32_t r;
    asm("cvt.rn.bf16x2.f32 %0, %1, %2;" : "=r"(r) : "f"(hi), "f"(lo));
    return r;
}
__device__ __forceinline__ uint32_t losplit(uint32_t hp, float v1, float v0) {
    float f0 = __uint_as_float(hp << 16);
    float f1 = __uint_as_float(hp & 0xffff0000u);
    return cvt2(v1 - f1, v0 - f0);
}
#define LDSM4(r, a) \
    asm volatile("ldmatrix.sync.aligned.m8n8.x4.shared.b16 {%0,%1,%2,%3}, [%4];" \
        : "=r"((r)[0]), "=r"((r)[1]), "=r"((r)[2]), "=r"((r)[3]) : "r"(a))
#define LDSM4T(r, a) \
    asm volatile("ldmatrix.sync.aligned.m8n8.x4.trans.shared.b16 {%0,%1,%2,%3}, [%4];" \
        : "=r"((r)[0]), "=r"((r)[1]), "=r"((r)[2]), "=r"((r)[3]) : "r"(a))
#define MMA(d, a, b) \
    asm volatile("mma.sync.aligned.m16n8k16.row.col.f32.bf16.bf16.f32 " \
        "{%0,%1,%2,%3}, {%4,%5,%6,%7}, {%8,%9}, {%0,%1,%2,%3};" \
        : "+f"((d)[0]), "+f"((d)[1]), "+f"((d)[2]), "+f"((d)[3]) \
        : "r"((a)[0]), "r"((a)[1]), "r"((a)[2]), "r"((a)[3]), "r"((b)[0]), "r"((b)[1]))

// -------------------- conversions --------------------
struct bh4 { bf a, b, c, d; };
__global__ void split_bf16(const float4* __restrict__ s, bf* __restrict__ hi,
                           bf* __restrict__ lo) {
    int i = blockIdx.x * 256 + threadIdx.x;
    float4 v = s[i];
    bf hx = __float2bfloat16(v.x), hy = __float2bfloat16(v.y);
    bf hz = __float2bfloat16(v.z), hw = __float2bfloat16(v.w);
    bh4 h = {hx, hy, hz, hw};
    bh4 l = {__float2bfloat16(v.x - __bfloat162float(hx)),
             __float2bfloat16(v.y - __bfloat162float(hy)),
             __float2bfloat16(v.z - __bfloat162float(hz)),
             __float2bfloat16(v.w - __bfloat162float(hw))};
    *(bh4*)(hi + 4 * i) = h;
    *(bh4*)(lo + 4 * i) = l;
}
__global__ void transpose_split(const float* __restrict__ W, bf* __restrict__ hi,
                                bf* __restrict__ lo, int K, int N) {
    __shared__ float t[32][33];
    const int n0 = blockIdx.x * 32, k0 = blockIdx.y * 32;
    const int tx = threadIdx.x, ty = threadIdx.y;
#pragma unroll
    for (int i = 0; i < 4; i++)
        t[ty + 8 * i][tx] = W[(k0 + ty + 8 * i) * N + n0 + tx];
    __syncthreads();
#pragma unroll
    for (int i = 0; i < 4; i++) {
        float v = t[tx][ty + 8 * i];
        bf h = __float2bfloat16(v);
        bf l = __float2bfloat16(v - __bfloat162float(h));
        int o = (n0 + ty + 8 * i) * K + k0 + tx;
        hi[o] = h; lo[o] = l;
    }
}

// -------------------- GEMM: CTA 256x128, warp 64x64, 3-stage --------------------
#define CH 32
#define SAHI 0
#define SALO 20480
#define SBHI 40960
#define SBLO 51200
#define STG 61440
#define GEMM_SMEM (3 * STG)

template <int EPI>
__global__ __launch_bounds__(256, 1) void mma_gemm(
    const bf* __restrict__ Ahi, const bf* __restrict__ Alo,
    const bf* __restrict__ Bhi, const bf* __restrict__ Blo,
    const float* __restrict__ bias, float* __restrict__ Cout, int Ncols)
{
    extern __shared__ __align__(128) char smem[];
    const uint32_t sb = s2u(smem);
    const int tid = threadIdx.x, wid = tid >> 5, lane = tid & 31;
    const int warpM = wid & 3, warpN = wid >> 2;          // 4 x 2 grid, warp 64x64
    const int rowBase = blockIdx.y * 256, colBase = blockIdx.x * 128;
    const bf* Ah = Ahi + rowBase * KK;
    const bf* Al = Alo + rowBase * KK;
    const bf* Bh = Bhi + colBase * KK;
    const bf* Bl = Blo + colBase * KK;

    float acc[4][8][4];
#pragma unroll
    for (int i = 0; i < 4; i++)
#pragma unroll
        for (int j = 0; j < 8; j++)
#pragma unroll
            for (int q = 0; q < 4; q++) acc[i][j][q] = 0.f;

    const uint32_t aOff = (uint32_t)((warpM * 64 + (lane & 15)) * 80 + (lane >> 4) * 16);
    const uint32_t bOff = (uint32_t)((warpN * 64 + ((lane >> 4) << 3) + (lane & 7)) * 80 +
                                     ((lane >> 3) & 1) * 16);

#define LOADC(c)                                                       \
    do {                                                               \
        const uint32_t st_ = sb + ((c) % 3) * STG;                     \
        const int k0_ = (c) * CH;                                      \
        _Pragma("unroll")                                              \
        for (int it = 0; it < 4; it++) {                               \
            int idx = tid + it * 256, r = idx >> 2, q = idx & 3;       \
            uint32_t d = (uint32_t)(r * 80 + q * 16);                  \
            int g = r * KK + k0_ + q * 8;                              \
            cpa16s(st_ + SAHI + d, Ah + g);                            \
            cpa16s(st_ + SALO + d, Al + g);                            \
        }                                                              \
        _Pragma("unroll")                                              \
        for (int it = 0; it < 2; it++) {                               \
            int idx = tid + it * 256, r = idx >> 2, q = idx & 3;       \
            uint32_t d = (uint32_t)(r * 80 + q * 16);                  \
            int g = r * KK + k0_ + q * 8;                              \
            cpa16s(st_ + SBHI + d, Bh + g);                            \
            cpa16s(st_ + SBLO + d, Bl + g);                            \
        }                                                              \
        cpa_commit();                                                  \
    } while (0)

    LOADC(0); LOADC(1);
    const int NC = KK / CH;
    for (int c = 0; c < NC; c++) {
        CPA_WAIT(1);
        __syncthreads();
        if (c + 2 < NC) LOADC(c + 2); else cpa_commit();
        const uint32_t st = sb + (c % 3) * STG;
#pragma unroll
        for (int ks = 0; ks < 2; ks++) {
            uint32_t ah[4][4], al[4][4], bh[4][4], bl[4][4];
#pragma unroll
            for (int mt = 0; mt < 4; mt++) {
                const uint32_t a = st + aOff + mt * (16 * 80) + ks * 32;
                LDSM4(ah[mt], a); LDSM4(al[mt], a + SALO);
            }
#pragma unroll
            for (int ng = 0; ng < 4; ng++) {
                const uint32_t a = st + SBHI + bOff + ng * (16 * 80) + ks * 32;
                LDSM4(bh[ng], a); LDSM4(bl[ng], a + (SBLO - SBHI));
            }
#pragma unroll
            for (int mt = 0; mt < 4; mt++)
#pragma unroll
                for (int ng = 0; ng < 4; ng++)
#pragma unroll
                    for (int sub = 0; sub < 2; sub++) {
                        const int n8 = ng * 2 + sub;
                        MMA(acc[mt][n8], ah[mt], (&bh[ng][sub * 2]));
                        MMA(acc[mt][n8], ah[mt], (&bl[ng][sub * 2]));
                        MMA(acc[mt][n8], al[mt], (&bh[ng][sub * 2]));
                    }
        }
    }
#undef LOADC

#pragma unroll
    for (int mt = 0; mt < 4; mt++) {
        const int rowT = rowBase + warpM * 64 + mt * 16 + (lane >> 2);
#pragma unroll
        for (int n8 = 0; n8 < 8; n8++) {
            const int col0 = colBase + warpN * 64 + n8 * 8 + ((lane & 3) << 1);
            const float2 b2 = *(const float2*)&bias[col0];
            float v0 = acc[mt][n8][0] + b2.x, v1 = acc[mt][n8][1] + b2.y;
            float v2 = acc[mt][n8][2] + b2.x, v3 = acc[mt][n8][3] + b2.y;
            if (EPI == 0) {
                const int which = col0 >> 10;
                const int hh = (col0 & 1023) >> 6, dd = col0 & 63;
                if (which == 0) { v0 *= 0.125f; v1 *= 0.125f; v2 *= 0.125f; v3 *= 0.125f; }
                bf* dh = (which == 0) ? g_qhi : (which == 1) ? g_khi : g_vhi;
                bf* dl = (which == 0) ? g_qlo : (which == 1) ? g_klo : g_vlo;
                const int o1 = ((((rowT >> 11) * Hh + hh) * Nn + (rowT & 2047)) << 6) + dd;
                const int rw = rowT + 8;
                const int o2 = ((((rw >> 11) * Hh + hh) * Nn + (rw & 2047)) << 6) + dd;
                uint32_t h0 = cvt2(v1, v0), h1 = cvt2(v3, v2);
                *(uint32_t*)(dh + o1) = h0;
                *(uint32_t*)(dl + o1) = losplit(h0, v1, v0);
                *(uint32_t*)(dh + o2) = h1;
                *(uint32_t*)(dl + o2) = losplit(h1, v3, v2);
            } else {
                *(float2*)&Cout[rowT * Ncols + col0] = make_float2(v0, v1);
                *(float2*)&Cout[(rowT + 8) * Ncols + col0] = make_float2(v2, v3);
            }
        }
    }
}

// -------------------- attention (mma.sync bf16) --------------------
#define PIT 144
#define AQH 0
#define AQL 18432
#define AST 36864
#define ASTB 73728
#define AMB 184320
#define ATTN_SMEM (AMB + 1024)

__global__ __launch_bounds__(256, 1) void attn_mma(const uint8_t* __restrict__ mask)
{
    extern __shared__ __align__(128) char smc[];
    const uint32_t sb = s2u(smc);
    float* maskb = (float*)(smc + AMB);
    const int tid = threadIdx.x, wid = tid >> 5, lane = tid & 31;
    const int qblk = blockIdx.x, h = blockIdx.y, b = blockIdx.z;
    const int bh_ = (b * Hh + h) * Nn;
    const bf* qh = g_qhi + (bh_ + qblk * 128) * Dh;
    const bf* ql = g_qlo + (bh_ + qblk * 128) * Dh;
    const bf* kh = g_khi + bh_ * Dh;
    const bf* kl = g_klo + bh_ * Dh;
    const bf* vh = g_vhi + bh_ * Dh;
    const bf* vl = g_vlo + bh_ * Dh;
    const uint8_t* mrow = mask + b * Nn;

#pragma unroll
    for (int it = 0; it < 4; it++) {
        int idx = tid + it * 256, r = idx >> 3, c = idx & 7;
        uint32_t off = (uint32_t)(r * PIT + c * 16);
        cpa16s(sb + AQH + off, qh + r * Dh + c * 8);
        cpa16s(sb + AQL + off, ql + r * Dh + c * 8);
    }
    cpa_commit();

#define LOADKV(kt)                                                          \
    do {                                                                    \
        const uint32_t base = sb + AST + ((kt) & 1) * ASTB;                 \
        _Pragma("unroll")                                                   \
        for (int it = 0; it < 4; it++) {                                    \
            int idx = tid + it * 256, r = idx >> 3, c = idx & 7;            \
            uint32_t off = (uint32_t)(r * PIT + c * 16);                    \
            int gs = ((kt) * 128 + r) * Dh + c * 8;                         \
            cpa16s(base + off, kh + gs);                                    \
            cpa16s(base + 18432 + off, kl + gs);                            \
            cpa16s(base + 36864 + off, vh + gs);                            \
            cpa16s(base + 55296 + off, vl + gs);                            \
        }                                                                   \
        cpa_commit();                                                       \
        if (tid < 128)                                                      \
            maskb[((kt) & 1) * 128 + tid] = mrow[(kt) * 128 + tid] ? -1e30f : 0.f; \
    } while (0)

    LOADKV(0);

    float oacc[8][4];
#pragma unroll
    for (int j = 0; j < 8; j++)
#pragma unroll
        for (int q = 0; q < 4; q++) oacc[j][q] = 0.f;
    float m0 = -1e30f, m1 = -1e30f, l0 = 0.f, l1 = 0.f;

    const uint32_t aOffQ = sb + (uint32_t)((wid * 16 + (lane & 15)) * PIT + (lane >> 4) * 16);
    const uint32_t bOffK = (uint32_t)((((lane >> 4) << 3) + (lane & 7)) * PIT +
                                      ((lane >> 3) & 1) * 16);
    const uint32_t vOff = (uint32_t)(((lane & 7) + ((lane >> 3) & 1) * 8) * PIT +
                                     (lane >> 4) * 16);

    for (int kt = 0; kt < Nn / 128; kt++) {
        CPA_WAIT(0);
        __syncthreads();
        if (kt + 1 < Nn / 128) LOADKV(kt + 1);
        const uint32_t st = sb + AST + (kt & 1) * ASTB;

        float sacc[16][4];
#pragma unroll
        for (int j = 0; j < 16; j++)
#pragma unroll
            for (int q = 0; q < 4; q++) sacc[j][q] = 0.f;

#pragma unroll
        for (int kk = 0; kk < 4; kk++) {
            uint32_t qa[4], qb_[4];
            LDSM4(qa, aOffQ + kk * 32);
            LDSM4(qb_, aOffQ + 18432 + kk * 32);
#pragma unroll
            for (int nt = 0; nt < 8; nt++) {
                uint32_t kA = st + bOffK + (uint32_t)(nt * 16 * PIT) + kk * 32;
                uint32_t kbh[4], kbl[4];
                LDSM4(kbh, kA);
                LDSM4(kbl, kA + 18432);
#pragma unroll
                for (int sub = 0; sub < 2; sub++) {
                    const int j = nt * 2 + sub;
                    MMA(sacc[j], qa, (&kbh[sub * 2]));
                    MMA(sacc[j], qa, (&kbl[sub * 2]));
                    MMA(sacc[j], qb_, (&kbh[sub * 2]));
                }
            }
        }

        float nm0 = m0, nm1 = m1;
        const float* mb = maskb + (kt & 1) * 128 + ((lane & 3) << 1);
#pragma unroll
        for (int j = 0; j < 16; j++) {
            float2 mv = *(const float2*)(mb + j * 8);
            sacc[j][0] += mv.x; sacc[j][1] += mv.y;
            sacc[j][2] += mv.x; sacc[j][3] += mv.y;
            nm0 = fmaxf(nm0, fmaxf(sacc[j][0], sacc[j][1]));
            nm1 = fmaxf(nm1, fmaxf(sacc[j][2], sacc[j][3]));
        }
        nm0 = fmaxf(nm0, __shfl_xor_sync(0xffffffffu, nm0, 1));
        nm0 = fmaxf(nm0, __shfl_xor_sync(0xffffffffu, nm0, 2));
        nm1 = fmaxf(nm1, __shfl_xor_sync(0xffffffffu, nm1, 1));
        nm1 = fmaxf(nm1, __shfl_xor_sync(0xffffffffu, nm1, 2));
        const float a0 = __expf(m0 - nm0), a1 = __expf(m1 - nm1);
        float s0 = 0.f, s1 = 0.f;
#pragma unroll
        for (int j = 0; j < 16; j++) {
            sacc[j][0] = __expf(sacc[j][0] - nm0);
            sacc[j][1] = __expf(sacc[j][1] - nm0);
            sacc[j][2] = __expf(sacc[j][2] - nm1);
            sacc[j][3] = __expf(sacc[j][3] - nm1);
            s0 += sacc[j][0] + sacc[j][1];
            s1 += sacc[j][2] + sacc[j][3];
        }
        s0 += __shfl_xor_sync(0xffffffffu, s0, 1);
        s0 += __shfl_xor_sync(0xffffffffu, s0, 2);
        s1 += __shfl_xor_sync(0xffffffffu, s1, 1);
        s1 += __shfl_xor_sync(0xffffffffu, s1, 2);
        l0 = a0 * l0 + s0; l1 = a1 * l1 + s1;
        m0 = nm0; m1 = nm1;
#pragma unroll
        for (int j = 0; j < 8; j++) {
            oacc[j][0] *= a0; oacc[j][1] *= a0;
            oacc[j][2] *= a1; oacc[j][3] *= a1;
        }

        const uint32_t vb = st + 36864;
#pragma unroll
        for (int kk2 = 0; kk2 < 8; kk2++) {
            const int f0 = kk2 * 2, f1 = f0 + 1;
            uint32_t ph[4], pl[4];
            ph[0] = cvt2(sacc[f0][1], sacc[f0][0]);
            ph[1] = cvt2(sacc[f0][3], sacc[f0][2]);
            ph[2] = cvt2(sacc[f1][1], sacc[f1][0]);
            ph[3] = cvt2(sacc[f1][3], sacc[f1][2]);
            pl[0] = losplit(ph[0], sacc[f0][1], sacc[f0][0]);
            pl[1] = losplit(ph[1], sacc[f0][3], sacc[f0][2]);
            pl[2] = losplit(ph[2], sacc[f1][1], sacc[f1][0]);
            pl[3] = losplit(ph[3], sacc[f1][3], sacc[f1][2]);
#pragma unroll
            for (int nt = 0; nt < 4; nt++) {
                const uint32_t va = vb + (uint32_t)(kk2 * 16 * PIT) + nt * 32 + vOff;
                uint32_t fh[4], fl[4];
                LDSM4T(fh, va);
                LDSM4T(fl, va + 18432);
#pragma unroll
                for (int sub = 0; sub < 2; sub++) {
                    const int n8 = nt * 2 + sub;
                    MMA(oacc[n8], ph, (&fh[sub * 2]));
                    MMA(oacc[n8], ph, (&fl[sub * 2]));
                    MMA(oacc[n8], pl, (&fh[sub * 2]));
                }
            }
        }
    }
#undef LOADKV

    // epilogue: write bf16 hi/lo directly (no fp32 g_ao, no split pass)
    const float i0 = 1.f / l0, i1 = 1.f / l1;
    const int q0 = qblk * 128 + wid * 16 + (lane >> 2);
    const int base0 = (b * Nn + q0) * Cc + h * Dh;
    const int base1 = base0 + 8 * Cc;
#pragma unroll
    for (int n8 = 0; n8 < 8; n8++) {
        const int col = n8 * 8 + ((lane & 3) << 1);
        float v0 = oacc[n8][0] * i0, v1 = oacc[n8][1] * i0;
        float v2 = oacc[n8][2] * i1, v3 = oacc[n8][3] * i1;
        uint32_t h0 = cvt2(v1, v0), h1 = cvt2(v3, v2);
        *(uint32_t*)(g_aohi + base0 + col) = h0;
        *(uint32_t*)(g_aolo + base0 + col) = losplit(h0, v1, v0);
        *(uint32_t*)(g_aohi + base1 + col) = h1;
        *(uint32_t*)(g_aolo + base1 + col) = losplit(h1, v3, v2);
    }
}

// ---------------------------------------------------------------------------
extern "C" void kernel_launch(void* const* d_in, const int* in_sizes, int n_in,
                              void* d_out, int out_size)
{
    (void)in_sizes; (void)n_in; (void)out_size;
    const float* x      = (const float*)d_in[0];
    const uint8_t* mask = (const uint8_t*)d_in[1];
    const float* Wqkv   = (const float*)d_in[2];
    const float* bqkv   = (const float*)d_in[3];
    const float* Wproj  = (const float*)d_in[4];
    const float* bproj  = (const float*)d_in[5];
    float* out = (float*)d_out;

    bf *xhi, *xlo, *aohi, *aolo, *wqh, *wql, *wph, *wpl;
    cudaGetSymbolAddress((void**)&xhi, g_xhi);
    cudaGetSymbolAddress((void**)&xlo, g_xlo);
    cudaGetSymbolAddress((void**)&aohi, g_aohi);
    cudaGetSymbolAddress((void**)&aolo, g_aolo);
    cudaGetSymbolAddress((void**)&wqh, g_wqt_hi);
    cudaGetSymbolAddress((void**)&wql, g_wqt_lo);
    cudaGetSymbolAddress((void**)&wph, g_wpt_hi);
    cudaGetSymbolAddress((void**)&wpl, g_wpt_lo);

    const int NE = Bb * Nn * Cc;
    split_bf16<<<NE / 4 / 256, 256>>>((const float4*)x, xhi, xlo);
    transpose_split<<<dim3(3 * Cc / 32, Cc / 32), dim3(32, 8)>>>(Wqkv, wqh, wql, Cc, 3 * Cc);
    transpose_split<<<dim3(Cc / 32, Cc / 32), dim3(32, 8)>>>(Wproj, wph, wpl, Cc, Cc);

    cudaFuncSetAttribute(mma_gemm<0>, cudaFuncAttributeMaxDynamicSharedMemorySize, GEMM_SMEM);
    mma_gemm<0><<<dim3(3 * Cc / 128, Bb * Nn / 256), 256, GEMM_SMEM>>>(
        xhi, xlo, wqh, wql, bqkv, nullptr, 3 * Cc);

    cudaFuncSetAttribute(attn_mma, cudaFuncAttributeMaxDynamicSharedMemorySize, ATTN_SMEM);
    attn_mma<<<dim3(Nn / 128, Hh, Bb), 256, ATTN_SMEM>>>(mask);

    cudaFuncSetAttribute(mma_gemm<1>, cudaFuncAttributeMaxDynamicSharedMemorySize, GEMM_SMEM);
    mma_gemm<1><<<dim3(Cc / 128, Bb * Nn / 256), 256, GEMM_SMEM>>>(
        aohi, aolo, wph, wpl, bproj, out, Cc);
}

// round 15
// speedup vs baseline: 1.9896x; 1.0805x over previous
#include <cuda_runtime.h>
#include <cuda_bf16.h>
#include <stdint.h>

#define Bb 4
#define Nn 2048
#define Cc 1024
#define Hh 16
#define Dh 64
#define KK 1024
typedef __nv_bfloat16 bf;

__device__ bf g_xhi[Bb * Nn * Cc];
__device__ bf g_xlo[Bb * Nn * Cc];
__device__ bf g_aohi[Bb * Nn * Cc];
__device__ bf g_aolo[Bb * Nn * Cc];
__device__ bf g_qhi[Bb * Hh * Nn * Dh];
__device__ bf g_qlo[Bb * Hh * Nn * Dh];
__device__ bf g_khi[Bb * Hh * Nn * Dh];
__device__ bf g_klo[Bb * Hh * Nn * Dh];
__device__ bf g_vhi[Bb * Hh * Nn * Dh];
__device__ bf g_vlo[Bb * Hh * Nn * Dh];
__device__ bf g_wqt_hi[3 * Cc * Cc];
__device__ bf g_wqt_lo[3 * Cc * Cc];
__device__ bf g_wpt_hi[Cc * Cc];
__device__ bf g_wpt_lo[Cc * Cc];

__device__ __forceinline__ void cpa16s(uint32_t sa, const void* g) {
    asm volatile("cp.async.cg.shared.global [%0], [%1], 16;" :: "r"(sa), "l"(g));
}
__device__ __forceinline__ void cpa_commit() {
    asm volatile("cp.async.commit_group;" ::: "memory");
}
#define CPA_WAIT(n) asm volatile("cp.async.wait_group %0;" :: "n"(n) : "memory")
__device__ __forceinline__ uint32_t s2u(const void* p) {
    uint32_t a;
    asm("{ .reg .u64 t; cvta.to.shared.u64 t, %1; cvt.u32.u64 %0, t; }" : "=r"(a) : "l"(p));
    return a;
}
__device__ __forceinline__ uint32_t cvt2(float hi, float lo) {
    uint32_t r;
    asm("cvt.rn.bf16x2.f32 %0, %1, %2;" : "=r"(r) : "f"(hi), "f"(lo));
    return r;
}
__device__ __forceinline__ uint32_t losplit(uint32_t hp, float v1, float v0) {
    float f0 = __uint_as_float(hp << 16);
    float f1 = __uint_as_float(hp & 0xffff0000u);
    return cvt2(v1 - f1, v0 - f0);
}
#define LDSM4(r, a) \
    asm volatile("ldmatrix.sync.aligned.m8n8.x4.shared.b16 {%0,%1,%2,%3}, [%4];" \
        : "=r"((r)[0]), "=r"((r)[1]), "=r"((r)[2]), "=r"((r)[3]) : "r"(a))
#define LDSM4T(r, a) \
    asm volatile("ldmatrix.sync.aligned.m8n8.x4.trans.shared.b16 {%0,%1,%2,%3}, [%4];" \
        : "=r"((r)[0]), "=r"((r)[1]), "=r"((r)[2]), "=r"((r)[3]) : "r"(a))
#define MMA(d, a, b) \
    asm volatile("mma.sync.aligned.m16n8k16.row.col.f32.bf16.bf16.f32 " \
        "{%0,%1,%2,%3}, {%4,%5,%6,%7}, {%8,%9}, {%0,%1,%2,%3};" \
        : "+f"((d)[0]), "+f"((d)[1]), "+f"((d)[2]), "+f"((d)[3]) \
        : "r"((a)[0]), "r"((a)[1]), "r"((a)[2]), "r"((a)[3]), "r"((b)[0]), "r"((b)[1]))

// -------------------- conversions --------------------
struct bh4 { bf a, b, c, d; };
__global__ void split_bf16(const float4* __restrict__ s, bf* __restrict__ hi,
                           bf* __restrict__ lo) {
    int i = blockIdx.x * 256 + threadIdx.x;
    float4 v = s[i];
    bf hx = __float2bfloat16(v.x), hy = __float2bfloat16(v.y);
    bf hz = __float2bfloat16(v.z), hw = __float2bfloat16(v.w);
    bh4 h = {hx, hy, hz, hw};
    bh4 l = {__float2bfloat16(v.x - __bfloat162float(hx)),
             __float2bfloat16(v.y - __bfloat162float(hy)),
             __float2bfloat16(v.z - __bfloat162float(hz)),
             __float2bfloat16(v.w - __bfloat162float(hw))};
    *(bh4*)(hi + 4 * i) = h;
    *(bh4*)(lo + 4 * i) = l;
}
__global__ void transpose_split(const float* __restrict__ W, bf* __restrict__ hi,
                                bf* __restrict__ lo, int K, int N) {
    __shared__ float t[32][33];
    const int n0 = blockIdx.x * 32, k0 = blockIdx.y * 32;
    const int tx = threadIdx.x, ty = threadIdx.y;
#pragma unroll
    for (int i = 0; i < 4; i++)
        t[ty + 8 * i][tx] = W[(k0 + ty + 8 * i) * N + n0 + tx];
    __syncthreads();
#pragma unroll
    for (int i = 0; i < 4; i++) {
        float v = t[tx][ty + 8 * i];
        bf h = __float2bfloat16(v);
        bf l = __float2bfloat16(v - __bfloat162float(h));
        int o = (n0 + ty + 8 * i) * K + k0 + tx;
        hi[o] = h; lo[o] = l;
    }
}

// ---------- GEMM: CTA 128x128, warp 32x64, 2-stage, 2 CTAs/SM ----------
#define CH 32
#define SAHI 0
#define SALO 10240
#define SBHI 20480
#define SBLO 30720
#define STG 40960
#define GEMM_SMEM (2 * STG)

template <int EPI>
__global__ __launch_bounds__(256, 2) void mma_gemm(
    const bf* __restrict__ Ahi, const bf* __restrict__ Alo,
    const bf* __restrict__ Bhi, const bf* __restrict__ Blo,
    const float* __restrict__ bias, float* __restrict__ Cout, int Ncols)
{
    extern __shared__ __align__(128) char smem[];
    const uint32_t sb = s2u(smem);
    const int tid = threadIdx.x, wid = tid >> 5, lane = tid & 31;
    const int warpM = wid & 3, warpN = wid >> 2;          // 4x2, warp 32x64
    const int rowBase = blockIdx.y * 128, colBase = blockIdx.x * 128;
    const bf* Ah = Ahi + rowBase * KK;
    const bf* Al = Alo + rowBase * KK;
    const bf* Bh = Bhi + colBase * KK;
    const bf* Bl = Blo + colBase * KK;

    float acc[2][8][4];
#pragma unroll
    for (int i = 0; i < 2; i++)
#pragma unroll
        for (int j = 0; j < 8; j++)
#pragma unroll
            for (int q = 0; q < 4; q++) acc[i][j][q] = 0.f;

    const uint32_t aOff = (uint32_t)((warpM * 32 + (lane & 15)) * 80 + (lane >> 4) * 16);
    const uint32_t bOff = (uint32_t)((warpN * 64 + ((lane >> 4) << 3) + (lane & 7)) * 80 +
                                     ((lane >> 3) & 1) * 16);

#define LOADC(c)                                                       \
    do {                                                               \
        const uint32_t st_ = sb + ((c) & 1) * STG;                     \
        const int k0_ = (c) * CH;                                      \
        _Pragma("unroll")                                              \
        for (int it = 0; it < 2; it++) {                               \
            int idx = tid + it * 256, r = idx >> 2, q = idx & 3;       \
            uint32_t d = (uint32_t)(r * 80 + q * 16);                  \
            int g = r * KK + k0_ + q * 8;                              \
            cpa16s(st_ + SAHI + d, Ah + g);                            \
            cpa16s(st_ + SALO + d, Al + g);                            \
            cpa16s(st_ + SBHI + d, Bh + g);                            \
            cpa16s(st_ + SBLO + d, Bl + g);                            \
        }                                                              \
        cpa_commit();                                                  \
    } while (0)

    LOADC(0);
    const int NC = KK / CH;
    for (int c = 0; c < NC; c++) {
        __syncthreads();              // all warps done reading stage (c&1)'s prev data
        if (c + 1 < NC) { LOADC(c + 1); CPA_WAIT(1); }
        else CPA_WAIT(0);
        __syncthreads();              // stage c visible to all
        const uint32_t st = sb + (c & 1) * STG;
#pragma unroll
        for (int ks = 0; ks < 2; ks++) {
            uint32_t ah[2][4], al[2][4];
#pragma unroll
            for (int mt = 0; mt < 2; mt++) {
                const uint32_t a = st + aOff + mt * (16 * 80) + ks * 32;
                LDSM4(ah[mt], a); LDSM4(al[mt], a + SALO);
            }
#pragma unroll
            for (int ng = 0; ng < 4; ng++) {
                uint32_t bh[4], bl[4];
                const uint32_t a = st + SBHI + bOff + ng * (16 * 80) + ks * 32;
                LDSM4(bh, a); LDSM4(bl, a + (SBLO - SBHI));
#pragma unroll
                for (int mt = 0; mt < 2; mt++)
#pragma unroll
                    for (int sub = 0; sub < 2; sub++) {
                        const int n8 = ng * 2 + sub;
                        MMA(acc[mt][n8], ah[mt], (&bh[sub * 2]));
                        MMA(acc[mt][n8], ah[mt], (&bl[sub * 2]));
                        MMA(acc[mt][n8], al[mt], (&bh[sub * 2]));
                    }
            }
        }
    }
#undef LOADC

#pragma unroll
    for (int mt = 0; mt < 2; mt++) {
        const int rowT = rowBase + warpM * 32 + mt * 16 + (lane >> 2);
#pragma unroll
        for (int n8 = 0; n8 < 8; n8++) {
            const int col0 = colBase + warpN * 64 + n8 * 8 + ((lane & 3) << 1);
            const float2 b2 = *(const float2*)&bias[col0];
            float v0 = acc[mt][n8][0] + b2.x, v1 = acc[mt][n8][1] + b2.y;
            float v2 = acc[mt][n8][2] + b2.x, v3 = acc[mt][n8][3] + b2.y;
            if (EPI == 0) {
                const int which = col0 >> 10;
                const int hh = (col0 & 1023) >> 6, dd = col0 & 63;
                if (which == 0) { v0 *= 0.125f; v1 *= 0.125f; v2 *= 0.125f; v3 *= 0.125f; }
                bf* dh = (which == 0) ? g_qhi : (which == 1) ? g_khi : g_vhi;
                bf* dl = (which == 0) ? g_qlo : (which == 1) ? g_klo : g_vlo;
                const int o1 = ((((rowT >> 11) * Hh + hh) * Nn + (rowT & 2047)) << 6) + dd;
                const int rw = rowT + 8;
                const int o2 = ((((rw >> 11) * Hh + hh) * Nn + (rw & 2047)) << 6) + dd;
                uint32_t h0 = cvt2(v1, v0), h1 = cvt2(v3, v2);
                *(uint32_t*)(dh + o1) = h0;
                *(uint32_t*)(dl + o1) = losplit(h0, v1, v0);
                *(uint32_t*)(dh + o2) = h1;
                *(uint32_t*)(dl + o2) = losplit(h1, v3, v2);
            } else {
                *(float2*)&Cout[rowT * Ncols + col0] = make_float2(v0, v1);
                *(float2*)&Cout[(rowT + 8) * Ncols + col0] = make_float2(v2, v3);
            }
        }
    }
}

// ---------- attention: 128q CTA, 64-key stages, 2 CTAs/SM ----------
#define PIT 144
#define AQH 0
#define AQL 18432
#define AST 36864
#define ASTB 36864          // per-stage: KH(9216) KL(9216) VH(9216) VL(9216)
#define AMB (AST + 2 * ASTB)
#define ATTN_SMEM (AMB + 1024)

__global__ __launch_bounds__(256, 2) void attn_mma(const uint8_t* __restrict__ mask)
{
    extern __shared__ __align__(128) char smc[];
    const uint32_t sb = s2u(smc);
    float* maskb = (float*)(smc + AMB);
    const int tid = threadIdx.x, wid = tid >> 5, lane = tid & 31;
    const int qblk = blockIdx.x, h = blockIdx.y, b = blockIdx.z;
    const int bh_ = (b * Hh + h) * Nn;
    const bf* qh = g_qhi + (bh_ + qblk * 128) * Dh;
    const bf* ql = g_qlo + (bh_ + qblk * 128) * Dh;
    const bf* kh = g_khi + bh_ * Dh;
    const bf* kl = g_klo + bh_ * Dh;
    const bf* vh = g_vhi + bh_ * Dh;
    const bf* vl = g_vlo + bh_ * Dh;
    const uint8_t* mrow = mask + b * Nn;

    // Q: 128 rows x 64 bf16, hi+lo
#pragma unroll
    for (int it = 0; it < 4; it++) {
        int idx = tid + it * 256, r = idx >> 3, c = idx & 7;
        uint32_t off = (uint32_t)(r * PIT + c * 16);
        cpa16s(sb + AQH + off, qh + r * Dh + c * 8);
        cpa16s(sb + AQL + off, ql + r * Dh + c * 8);
    }
    cpa_commit();

#define LOADKV(kt)                                                          \
    do {                                                                    \
        const uint32_t base = sb + AST + ((kt) & 1) * ASTB;                 \
        _Pragma("unroll")                                                   \
        for (int it = 0; it < 2; it++) {                                    \
            int idx = tid + it * 256, r = idx >> 3, c = idx & 7;            \
            uint32_t off = (uint32_t)(r * PIT + c * 16);                    \
            int gs = ((kt) * 64 + r) * Dh + c * 8;                          \
            cpa16s(base + off, kh + gs);                                    \
            cpa16s(base + 9216 + off, kl + gs);                             \
            cpa16s(base + 18432 + off, vh + gs);                            \
            cpa16s(base + 27648 + off, vl + gs);                            \
        }                                                                   \
        cpa_commit();                                                       \
        if (tid < 64)                                                       \
            maskb[((kt) & 1) * 64 + tid] = mrow[(kt) * 64 + tid] ? -1e30f : 0.f; \
    } while (0)

    LOADKV(0);

    float oacc[8][4];
#pragma unroll
    for (int j = 0; j < 8; j++)
#pragma unroll
        for (int q = 0; q < 4; q++) oacc[j][q] = 0.f;
    float m0 = -1e30f, m1 = -1e30f, l0 = 0.f, l1 = 0.f;

    const uint32_t aOffQ = sb + (uint32_t)((wid * 16 + (lane & 15)) * PIT + (lane >> 4) * 16);
    const uint32_t bOffK = (uint32_t)((((lane >> 4) << 3) + (lane & 7)) * PIT +
                                      ((lane >> 3) & 1) * 16);
    const uint32_t vOff = (uint32_t)(((lane & 7) + ((lane >> 3) & 1) * 8) * PIT +
                                     (lane >> 4) * 16);

    const int NT = Nn / 64;
    for (int kt = 0; kt < NT; kt++) {
        CPA_WAIT(0);
        __syncthreads();
        if (kt + 1 < NT) LOADKV(kt + 1);
        const uint32_t st = sb + AST + (kt & 1) * ASTB;

        float sacc[8][4];
#pragma unroll
        for (int j = 0; j < 8; j++)
#pragma unroll
            for (int q = 0; q < 4; q++) sacc[j][q] = 0.f;

#pragma unroll
        for (int kk = 0; kk < 4; kk++) {
            uint32_t qa[4], qb_[4];
            LDSM4(qa, aOffQ + kk * 32);
            LDSM4(qb_, aOffQ + 18432 + kk * 32);
#pragma unroll
            for (int nt = 0; nt < 4; nt++) {
                uint32_t kA = st + bOffK + (uint32_t)(nt * 16 * PIT) + kk * 32;
                uint32_t kbh[4], kbl[4];
                LDSM4(kbh, kA);
                LDSM4(kbl, kA + 9216);
#pragma unroll
                for (int sub = 0; sub < 2; sub++) {
                    const int j = nt * 2 + sub;
                    MMA(sacc[j], qa, (&kbh[sub * 2]));
                    MMA(sacc[j], qa, (&kbl[sub * 2]));
                    MMA(sacc[j], qb_, (&kbh[sub * 2]));
                }
            }
        }

        float nm0 = m0, nm1 = m1;
        const float* mb = maskb + (kt & 1) * 64 + ((lane & 3) << 1);
#pragma unroll
        for (int j = 0; j < 8; j++) {
            float2 mv = *(const float2*)(mb + j * 8);
            sacc[j][0] += mv.x; sacc[j][1] += mv.y;
            sacc[j][2] += mv.x; sacc[j][3] += mv.y;
            nm0 = fmaxf(nm0, fmaxf(sacc[j][0], sacc[j][1]));
            nm1 = fmaxf(nm1, fmaxf(sacc[j][2], sacc[j][3]));
        }
        nm0 = fmaxf(nm0, __shfl_xor_sync(0xffffffffu, nm0, 1));
        nm0 = fmaxf(nm0, __shfl_xor_sync(0xffffffffu, nm0, 2));
        nm1 = fmaxf(nm1, __shfl_xor_sync(0xffffffffu, nm1, 1));
        nm1 = fmaxf(nm1, __shfl_xor_sync(0xffffffffu, nm1, 2));
        const float a0 = __expf(m0 - nm0), a1 = __expf(m1 - nm1);
        float s0 = 0.f, s1 = 0.f;
#pragma unroll
        for (int j = 0; j < 8; j++) {
            sacc[j][0] = __expf(sacc[j][0] - nm0);
            sacc[j][1] = __expf(sacc[j][1] - nm0);
            sacc[j][2] = __expf(sacc[j][2] - nm1);
            sacc[j][3] = __expf(sacc[j][3] - nm1);
            s0 += sacc[j][0] + sacc[j][1];
            s1 += sacc[j][2] + sacc[j][3];
        }
        s0 += __shfl_xor_sync(0xffffffffu, s0, 1);
        s0 += __shfl_xor_sync(0xffffffffu, s0, 2);
        s1 += __shfl_xor_sync(0xffffffffu, s1, 1);
        s1 += __shfl_xor_sync(0xffffffffu, s1, 2);
        l0 = a0 * l0 + s0; l1 = a1 * l1 + s1;
        m0 = nm0; m1 = nm1;
#pragma unroll
        for (int j = 0; j < 8; j++) {
            oacc[j][0] *= a0; oacc[j][1] *= a0;
            oacc[j][2] *= a1; oacc[j][3] *= a1;
        }

        const uint32_t vb = st + 18432;
#pragma unroll
        for (int kk2 = 0; kk2 < 4; kk2++) {
            const int f0 = kk2 * 2, f1 = f0 + 1;
            uint32_t ph[4], pl[4];
            ph[0] = cvt2(sacc[f0][1], sacc[f0][0]);
            ph[1] = cvt2(sacc[f0][3], sacc[f0][2]);
            ph[2] = cvt2(sacc[f1][1], sacc[f1][0]);
            ph[3] = cvt2(sacc[f1][3], sacc[f1][2]);
            pl[0] = losplit(ph[0], sacc[f0][1], sacc[f0][0]);
            pl[1] = losplit(ph[1], sacc[f0][3], sacc[f0][2]);
            pl[2] = losplit(ph[2], sacc[f1][1], sacc[f1][0]);
            pl[3] = losplit(ph[3], sacc[f1][3], sacc[f1][2]);
#pragma unroll
            for (int nt = 0; nt < 4; nt++) {
                const uint32_t va = vb + (uint32_t)(kk2 * 16 * PIT) + nt * 32 + vOff;
                uint32_t fh[4], fl[4];
                LDSM4T(fh, va);
                LDSM4T(fl, va + 9216);
#pragma unroll
                for (int sub = 0; sub < 2; sub++) {
                    const int n8 = nt * 2 + sub;
                    MMA(oacc[n8], ph, (&fh[sub * 2]));
                    MMA(oacc[n8], ph, (&fl[sub * 2]));
                    MMA(oacc[n8], pl, (&fh[sub * 2]));
                }
            }
        }
    }
#undef LOADKV

    const float i0 = 1.f / l0, i1 = 1.f / l1;
    const int q0 = qblk * 128 + wid * 16 + (lane >> 2);
    const int base0 = (b * Nn + q0) * Cc + h * Dh;
    const int base1 = base0 + 8 * Cc;
#pragma unroll
    for (int n8 = 0; n8 < 8; n8++) {
        const int col = n8 * 8 + ((lane & 3) << 1);
        float v0 = oacc[n8][0] * i0, v1 = oacc[n8][1] * i0;
        float v2 = oacc[n8][2] * i1, v3 = oacc[n8][3] * i1;
        uint32_t h0 = cvt2(v1, v0), h1 = cvt2(v3, v2);
        *(uint32_t*)(g_aohi + base0 + col) = h0;
        *(uint32_t*)(g_aolo + base0 + col) = losplit(h0, v1, v0);
        *(uint32_t*)(g_aohi + base1 + col) = h1;
        *(uint32_t*)(g_aolo + base1 + col) = losplit(h1, v3, v2);
    }
}

// ---------------------------------------------------------------------------
extern "C" void kernel_launch(void* const* d_in, const int* in_sizes, int n_in,
                              void* d_out, int out_size)
{
    (void)in_sizes; (void)n_in; (void)out_size;
    const float* x      = (const float*)d_in[0];
    const uint8_t* mask = (const uint8_t*)d_in[1];
    const float* Wqkv   = (const float*)d_in[2];
    const float* bqkv   = (const float*)d_in[3];
    const float* Wproj  = (const float*)d_in[4];
    const float* bproj  = (const float*)d_in[5];
    float* out = (float*)d_out;

    bf *xhi, *xlo, *aohi, *aolo, *wqh, *wql, *wph, *wpl;
    cudaGetSymbolAddress((void**)&xhi, g_xhi);
    cudaGetSymbolAddress((void**)&xlo, g_xlo);
    cudaGetSymbolAddress((void**)&aohi, g_aohi);
    cudaGetSymbolAddress((void**)&aolo, g_aolo);
    cudaGetSymbolAddress((void**)&wqh, g_wqt_hi);
    cudaGetSymbolAddress((void**)&wql, g_wqt_lo);
    cudaGetSymbolAddress((void**)&wph, g_wpt_hi);
    cudaGetSymbolAddress((void**)&wpl, g_wpt_lo);

    const int NE = Bb * Nn * Cc;
    split_bf16<<<NE / 4 / 256, 256>>>((const float4*)x, xhi, xlo);
    transpose_split<<<dim3(3 * Cc / 32, Cc / 32), dim3(32, 8)>>>(Wqkv, wqh, wql, Cc, 3 * Cc);
    transpose_split<<<dim3(Cc / 32, Cc / 32), dim3(32, 8)>>>(Wproj, wph, wpl, Cc, Cc);

    cudaFuncSetAttribute(mma_gemm<0>, cudaFuncAttributeMaxDynamicSharedMemorySize, GEMM_SMEM);
    mma_gemm<0><<<dim3(3 * Cc / 128, Bb * Nn / 128), 256, GEMM_SMEM>>>(
        xhi, xlo, wqh, wql, bqkv, nullptr, 3 * Cc);

    cudaFuncSetAttribute(attn_mma, cudaFuncAttributeMaxDynamicSharedMemorySize, ATTN_SMEM);
    attn_mma<<<dim3(Nn / 128, Hh, Bb), 256, ATTN_SMEM>>>(mask);

    cudaFuncSetAttribute(mma_gemm<1>, cudaFuncAttributeMaxDynamicSharedMemorySize, GEMM_SMEM);
    mma_gemm<1><<<dim3(Cc / 128, Bb * Nn / 128), 256, GEMM_SMEM>>>(
        aohi, aolo, wph, wpl, bproj, out, Cc);
}

// round 17
// speedup vs baseline: 2.0157x; 1.0131x over previous
#include <cuda_runtime.h>
#include <cuda_bf16.h>
#include <stdint.h>

#define Bb 4
#define Nn 2048
#define Cc 1024
#define Hh 16
#define Dh 64
#define KK 1024
typedef __nv_bfloat16 bf;

__device__ bf g_xhi[Bb * Nn * Cc];
__device__ bf g_xlo[Bb * Nn * Cc];
__device__ bf g_aohi[Bb * Nn * Cc];
__device__ bf g_aolo[Bb * Nn * Cc];
__device__ bf g_qhi[Bb * Hh * Nn * Dh];
__device__ bf g_qlo[Bb * Hh * Nn * Dh];
__device__ bf g_khi[Bb * Hh * Nn * Dh];
__device__ bf g_klo[Bb * Hh * Nn * Dh];
__device__ bf g_vhi[Bb * Hh * Nn * Dh];
__device__ bf g_vlo[Bb * Hh * Nn * Dh];
__device__ bf g_wqt_hi[3 * Cc * Cc];
__device__ bf g_wqt_lo[3 * Cc * Cc];
__device__ bf g_wpt_hi[Cc * Cc];
__device__ bf g_wpt_lo[Cc * Cc];

__device__ __forceinline__ void cpa16s(uint32_t sa, const void* g) {
    asm volatile("cp.async.cg.shared.global [%0], [%1], 16;" :: "r"(sa), "l"(g));
}
__device__ __forceinline__ void cpa_commit() {
    asm volatile("cp.async.commit_group;" ::: "memory");
}
#define CPA_WAIT(n) asm volatile("cp.async.wait_group %0;" :: "n"(n) : "memory")
__device__ __forceinline__ uint32_t s2u(const void* p) {
    uint32_t a;
    asm("{ .reg .u64 t; cvta.to.shared.u64 t, %1; cvt.u32.u64 %0, t; }" : "=r"(a) : "l"(p));
    return a;
}
__device__ __forceinline__ uint32_t cvt2(float hi, float lo) {
    uint32_t r;
    asm("cvt.rn.bf16x2.f32 %0, %1, %2;" : "=r"(r) : "f"(hi), "f"(lo));
    return r;
}
__device__ __forceinline__ uint32_t losplit(uint32_t hp, float v1, float v0) {
    float f0 = __uint_as_float(hp << 16);
    float f1 = __uint_as_float(hp & 0xffff0000u);
    return cvt2(v1 - f1, v0 - f0);
}
#define LDSM4(r, a) \
    asm volatile("ldmatrix.sync.aligned.m8n8.x4.shared.b16 {%0,%1,%2,%3}, [%4];" \
        : "=r"((r)[0]), "=r"((r)[1]), "=r"((r)[2]), "=r"((r)[3]) : "r"(a))
#define LDSM4T(r, a) \
    asm volatile("ldmatrix.sync.aligned.m8n8.x4.trans.shared.b16 {%0,%1,%2,%3}, [%4];" \
        : "=r"((r)[0]), "=r"((r)[1]), "=r"((r)[2]), "=r"((r)[3]) : "r"(a))
#define MMA(d, a, b) \
    asm volatile("mma.sync.aligned.m16n8k16.row.col.f32.bf16.bf16.f32 " \
        "{%0,%1,%2,%3}, {%4,%5,%6,%7}, {%8,%9}, {%0,%1,%2,%3};" \
        : "+f"((d)[0]), "+f"((d)[1]), "+f"((d)[2]), "+f"((d)[3]) \
        : "r"((a)[0]), "r"((a)[1]), "r"((a)[2]), "r"((a)[3]), "r"((b)[0]), "r"((b)[1]))

// -------------------- conversions --------------------
struct bh4 { bf a, b, c, d; };
__global__ void split_bf16(const float4* __restrict__ s, bf* __restrict__ hi,
                           bf* __restrict__ lo) {
    int i = blockIdx.x * 256 + threadIdx.x;
    float4 v = s[i];
    bf hx = __float2bfloat16(v.x), hy = __float2bfloat16(v.y);
    bf hz = __float2bfloat16(v.z), hw = __float2bfloat16(v.w);
    bh4 h = {hx, hy, hz, hw};
    bh4 l = {__float2bfloat16(v.x - __bfloat162float(hx)),
             __float2bfloat16(v.y - __bfloat162float(hy)),
             __float2bfloat16(v.z - __bfloat162float(hz)),
             __float2bfloat16(v.w - __bfloat162float(hw))};
    *(bh4*)(hi + 4 * i) = h;
    *(bh4*)(lo + 4 * i) = l;
}
__global__ void transpose_split(const float* __restrict__ W, bf* __restrict__ hi,
                                bf* __restrict__ lo, int K, int N) {
    __shared__ float t[32][33];
    const int n0 = blockIdx.x * 32, k0 = blockIdx.y * 32;
    const int tx = threadIdx.x, ty = threadIdx.y;
#pragma unroll
    for (int i = 0; i < 4; i++)
        t[ty + 8 * i][tx] = W[(k0 + ty + 8 * i) * N + n0 + tx];
    __syncthreads();
#pragma unroll
    for (int i = 0; i < 4; i++) {
        float v = t[tx][ty + 8 * i];
        bf h = __float2bfloat16(v);
        bf l = __float2bfloat16(v - __bfloat162float(h));
        int o = (n0 + ty + 8 * i) * K + k0 + tx;
        hi[o] = h; lo[o] = l;
    }
}

// ---------- GEMM: CTA 128x128, warp 32x64, 2-stage, 2 CTAs/SM, 1 sync/chunk ----------
#define CH 32
#define SAHI 0
#define SALO 10240
#define SBHI 20480
#define SBLO 30720
#define STG 40960
#define GEMM_SMEM (2 * STG)

template <int EPI>
__global__ __launch_bounds__(256, 2) void mma_gemm(
    const bf* __restrict__ Ahi, const bf* __restrict__ Alo,
    const bf* __restrict__ Bhi, const bf* __restrict__ Blo,
    const float* __restrict__ bias, float* __restrict__ Cout, int Ncols)
{
    extern __shared__ __align__(128) char smem[];
    const uint32_t sb = s2u(smem);
    const int tid = threadIdx.x, wid = tid >> 5, lane = tid & 31;
    const int warpM = wid & 3, warpN = wid >> 2;          // 4x2, warp 32x64
    const int rowBase = blockIdx.y * 128, colBase = blockIdx.x * 128;
    const bf* Ah = Ahi + rowBase * KK;
    const bf* Al = Alo + rowBase * KK;
    const bf* Bh = Bhi + colBase * KK;
    const bf* Bl = Blo + colBase * KK;

    float acc[2][8][4];
#pragma unroll
    for (int i = 0; i < 2; i++)
#pragma unroll
        for (int j = 0; j < 8; j++)
#pragma unroll
            for (int q = 0; q < 4; q++) acc[i][j][q] = 0.f;

    const uint32_t aOff = (uint32_t)((warpM * 32 + (lane & 15)) * 80 + (lane >> 4) * 16);
    const uint32_t bOff = (uint32_t)((warpN * 64 + ((lane >> 4) << 3) + (lane & 7)) * 80 +
                                     ((lane >> 3) & 1) * 16);

#define LOADC(c)                                                       \
    do {                                                               \
        const uint32_t st_ = sb + ((c) & 1) * STG;                     \
        const int k0_ = (c) * CH;                                      \
        _Pragma("unroll")                                              \
        for (int it = 0; it < 2; it++) {                               \
            int idx = tid + it * 256, r = idx >> 2, q = idx & 3;       \
            uint32_t d = (uint32_t)(r * 80 + q * 16);                  \
            int g = r * KK + k0_ + q * 8;                              \
            cpa16s(st_ + SAHI + d, Ah + g);                            \
            cpa16s(st_ + SALO + d, Al + g);                            \
            cpa16s(st_ + SBHI + d, Bh + g);                            \
            cpa16s(st_ + SBLO + d, Bl + g);                            \
        }                                                              \
        cpa_commit();                                                  \
    } while (0)

    LOADC(0);
    const int NC = KK / CH;
    for (int c = 0; c < NC; c++) {
        CPA_WAIT(0);                  // stage c landed (only pending group)
        __syncthreads();              // publish stage c; all warps done with stage c-1
        if (c + 1 < NC) LOADC(c + 1); // overwrite stage c-1 (barrier-protected)
        const uint32_t st = sb + (c & 1) * STG;
#pragma unroll
        for (int ks = 0; ks < 2; ks++) {
            uint32_t ah[2][4], al[2][4];
#pragma unroll
            for (int mt = 0; mt < 2; mt++) {
                const uint32_t a = st + aOff + mt * (16 * 80) + ks * 32;
                LDSM4(ah[mt], a); LDSM4(al[mt], a + SALO);
            }
#pragma unroll
            for (int ng = 0; ng < 4; ng++) {
                uint32_t bh[4], bl[4];
                const uint32_t a = st + SBHI + bOff + ng * (16 * 80) + ks * 32;
                LDSM4(bh, a); LDSM4(bl, a + (SBLO - SBHI));
#pragma unroll
                for (int mt = 0; mt < 2; mt++)
#pragma unroll
                    for (int sub = 0; sub < 2; sub++) {
                        const int n8 = ng * 2 + sub;
                        MMA(acc[mt][n8], ah[mt], (&bh[sub * 2]));
                        MMA(acc[mt][n8], ah[mt], (&bl[sub * 2]));
                        MMA(acc[mt][n8], al[mt], (&bh[sub * 2]));
                    }
            }
        }
    }
#undef LOADC

#pragma unroll
    for (int mt = 0; mt < 2; mt++) {
        const int rowT = rowBase + warpM * 32 + mt * 16 + (lane >> 2);
#pragma unroll
        for (int n8 = 0; n8 < 8; n8++) {
            const int col0 = colBase + warpN * 64 + n8 * 8 + ((lane & 3) << 1);
            const float2 b2 = *(const float2*)&bias[col0];
            float v0 = acc[mt][n8][0] + b2.x, v1 = acc[mt][n8][1] + b2.y;
            float v2 = acc[mt][n8][2] + b2.x, v3 = acc[mt][n8][3] + b2.y;
            if (EPI == 0) {
                const int which = col0 >> 10;
                const int hh = (col0 & 1023) >> 6, dd = col0 & 63;
                if (which == 0) { v0 *= 0.125f; v1 *= 0.125f; v2 *= 0.125f; v3 *= 0.125f; }
                bf* dh = (which == 0) ? g_qhi : (which == 1) ? g_khi : g_vhi;
                bf* dl = (which == 0) ? g_qlo : (which == 1) ? g_klo : g_vlo;
                const int o1 = ((((rowT >> 11) * Hh + hh) * Nn + (rowT & 2047)) << 6) + dd;
                const int rw = rowT + 8;
                const int o2 = ((((rw >> 11) * Hh + hh) * Nn + (rw & 2047)) << 6) + dd;
                uint32_t h0 = cvt2(v1, v0), h1 = cvt2(v3, v2);
                *(uint32_t*)(dh + o1) = h0;
                *(uint32_t*)(dl + o1) = losplit(h0, v1, v0);
                *(uint32_t*)(dh + o2) = h1;
                *(uint32_t*)(dl + o2) = losplit(h1, v3, v2);
            } else {
                *(float2*)&Cout[rowT * Ncols + col0] = make_float2(v0, v1);
                *(float2*)&Cout[(rowT + 8) * Ncols + col0] = make_float2(v2, v3);
            }
        }
    }
}

// ---------- attention: 128q CTA, 64-key stages, 2 CTAs/SM ----------
#define PIT 144
#define AQH 0
#define AQL 18432
#define AST 36864
#define ASTB 36864          // per-stage: KH(9216) KL(9216) VH(9216) VL(9216)
#define AMB (AST + 2 * ASTB)
#define ATTN_SMEM (AMB + 1024)

__global__ __launch_bounds__(256, 2) void attn_mma(const uint8_t* __restrict__ mask)
{
    extern __shared__ __align__(128) char smc[];
    const uint32_t sb = s2u(smc);
    float* maskb = (float*)(smc + AMB);
    const int tid = threadIdx.x, wid = tid >> 5, lane = tid & 31;
    const int qblk = blockIdx.x, h = blockIdx.y, b = blockIdx.z;
    const int bh_ = (b * Hh + h) * Nn;
    const bf* qh = g_qhi + (bh_ + qblk * 128) * Dh;
    const bf* ql = g_qlo + (bh_ + qblk * 128) * Dh;
    const bf* kh = g_khi + bh_ * Dh;
    const bf* kl = g_klo + bh_ * Dh;
    const bf* vh = g_vhi + bh_ * Dh;
    const bf* vl = g_vlo + bh_ * Dh;
    const uint8_t* mrow = mask + b * Nn;

    // Q: 128 rows x 64 bf16, hi+lo
#pragma unroll
    for (int it = 0; it < 4; it++) {
        int idx = tid + it * 256, r = idx >> 3, c = idx & 7;
        uint32_t off = (uint32_t)(r * PIT + c * 16);
        cpa16s(sb + AQH + off, qh + r * Dh + c * 8);
        cpa16s(sb + AQL + off, ql + r * Dh + c * 8);
    }
    cpa_commit();

#define LOADKV(kt)                                                          \
    do {                                                                    \
        const uint32_t base = sb + AST + ((kt) & 1) * ASTB;                 \
        _Pragma("unroll")                                                   \
        for (int it = 0; it < 2; it++) {                                    \
            int idx = tid + it * 256, r = idx >> 3, c = idx & 7;            \
            uint32_t off = (uint32_t)(r * PIT + c * 16);                    \
            int gs = ((kt) * 64 + r) * Dh + c * 8;                          \
            cpa16s(base + off, kh + gs);                                    \
            cpa16s(base + 9216 + off, kl + gs);                             \
            cpa16s(base + 18432 + off, vh + gs);                            \
            cpa16s(base + 27648 + off, vl + gs);                            \
        }                                                                   \
        cpa_commit();                                                       \
        if (tid < 64)                                                       \
            maskb[((kt) & 1) * 64 + tid] = mrow[(kt) * 64 + tid] ? -1e30f : 0.f; \
    } while (0)

    LOADKV(0);

    float oacc[8][4];
#pragma unroll
    for (int j = 0; j < 8; j++)
#pragma unroll
        for (int q = 0; q < 4; q++) oacc[j][q] = 0.f;
    float m0 = -1e30f, m1 = -1e30f, l0 = 0.f, l1 = 0.f;

    const uint32_t aOffQ = sb + (uint32_t)((wid * 16 + (lane & 15)) * PIT + (lane >> 4) * 16);
    const uint32_t bOffK = (uint32_t)((((lane >> 4) << 3) + (lane & 7)) * PIT +
                                      ((lane >> 3) & 1) * 16);
    const uint32_t vOff = (uint32_t)(((lane & 7) + ((lane >> 3) & 1) * 8) * PIT +
                                     (lane >> 4) * 16);

    const int NT = Nn / 64;
    for (int kt = 0; kt < NT; kt++) {
        CPA_WAIT(0);
        __syncthreads();
        if (kt + 1 < NT) LOADKV(kt + 1);
        const uint32_t st = sb + AST + (kt & 1) * ASTB;

        float sacc[8][4];
#pragma unroll
        for (int j = 0; j < 8; j++)
#pragma unroll
            for (int q = 0; q < 4; q++) sacc[j][q] = 0.f;

#pragma unroll
        for (int kk = 0; kk < 4; kk++) {
            uint32_t qa[4], qb_[4];
            LDSM4(qa, aOffQ + kk * 32);
            LDSM4(qb_, aOffQ + 18432 + kk * 32);
#pragma unroll
            for (int nt = 0; nt < 4; nt++) {
                uint32_t kA = st + bOffK + (uint32_t)(nt * 16 * PIT) + kk * 32;
                uint32_t kbh[4], kbl[4];
                LDSM4(kbh, kA);
                LDSM4(kbl, kA + 9216);
#pragma unroll
                for (int sub = 0; sub < 2; sub++) {
                    const int j = nt * 2 + sub;
                    MMA(sacc[j], qa, (&kbh[sub * 2]));
                    MMA(sacc[j], qa, (&kbl[sub * 2]));
                    MMA(sacc[j], qb_, (&kbh[sub * 2]));
                }
            }
        }

        float nm0 = m0, nm1 = m1;
        const float* mb = maskb + (kt & 1) * 64 + ((lane & 3) << 1);
#pragma unroll
        for (int j = 0; j < 8; j++) {
            float2 mv = *(const float2*)(mb + j * 8);
            sacc[j][0] += mv.x; sacc[j][1] += mv.y;
            sacc[j][2] += mv.x; sacc[j][3] += mv.y;
            nm0 = fmaxf(nm0, fmaxf(sacc[j][0], sacc[j][1]));
            nm1 = fmaxf(nm1, fmaxf(sacc[j][2], sacc[j][3]));
        }
        nm0 = fmaxf(nm0, __shfl_xor_sync(0xffffffffu, nm0, 1));
        nm0 = fmaxf(nm0, __shfl_xor_sync(0xffffffffu, nm0, 2));
        nm1 = fmaxf(nm1, __shfl_xor_sync(0xffffffffu, nm1, 1));
        nm1 = fmaxf(nm1, __shfl_xor_sync(0xffffffffu, nm1, 2));
        const float a0 = __expf(m0 - nm0), a1 = __expf(m1 - nm1);
        float s0 = 0.f, s1 = 0.f;
#pragma unroll
        for (int j = 0; j < 8; j++) {
            sacc[j][0] = __expf(sacc[j][0] - nm0);
            sacc[j][1] = __expf(sacc[j][1] - nm0);
            sacc[j][2] = __expf(sacc[j][2] - nm1);
            sacc[j][3] = __expf(sacc[j][3] - nm1);
            s0 += sacc[j][0] + sacc[j][1];
            s1 += sacc[j][2] + sacc[j][3];
        }
        s0 += __shfl_xor_sync(0xffffffffu, s0, 1);
        s0 += __shfl_xor_sync(0xffffffffu, s0, 2);
        s1 += __shfl_xor_sync(0xffffffffu, s1, 1);
        s1 += __shfl_xor_sync(0xffffffffu, s1, 2);
        l0 = a0 * l0 + s0; l1 = a1 * l1 + s1;
        m0 = nm0; m1 = nm1;
#pragma unroll
        for (int j = 0; j < 8; j++) {
            oacc[j][0] *= a0; oacc[j][1] *= a0;
            oacc[j][2] *= a1; oacc[j][3] *= a1;
        }

        const uint32_t vb = st + 18432;
#pragma unroll
        for (int kk2 = 0; kk2 < 4; kk2++) {
            const int f0 = kk2 * 2, f1 = f0 + 1;
            uint32_t ph[4], pl[4];
            ph[0] = cvt2(sacc[f0][1], sacc[f0][0]);
            ph[1] = cvt2(sacc[f0][3], sacc[f0][2]);
            ph[2] = cvt2(sacc[f1][1], sacc[f1][0]);
            ph[3] = cvt2(sacc[f1][3], sacc[f1][2]);
            pl[0] = losplit(ph[0], sacc[f0][1], sacc[f0][0]);
            pl[1] = losplit(ph[1], sacc[f0][3], sacc[f0][2]);
            pl[2] = losplit(ph[2], sacc[f1][1], sacc[f1][0]);
            pl[3] = losplit(ph[3], sacc[f1][3], sacc[f1][2]);
#pragma unroll
            for (int nt = 0; nt < 4; nt++) {
                const uint32_t va = vb + (uint32_t)(kk2 * 16 * PIT) + nt * 32 + vOff;
                uint32_t fh[4], fl[4];
                LDSM4T(fh, va);
                LDSM4T(fl, va + 9216);
#pragma unroll
                for (int sub = 0; sub < 2; sub++) {
                    const int n8 = nt * 2 + sub;
                    MMA(oacc[n8], ph, (&fh[sub * 2]));
                    MMA(oacc[n8], ph, (&fl[sub * 2]));
                    MMA(oacc[n8], pl, (&fh[sub * 2]));
                }
            }
        }
    }
#undef LOADKV

    const float i0 = 1.f / l0, i1 = 1.f / l1;
    const int q0 = qblk * 128 + wid * 16 + (lane >> 2);
    const int base0 = (b * Nn + q0) * Cc + h * Dh;
    const int base1 = base0 + 8 * Cc;
#pragma unroll
    for (int n8 = 0; n8 < 8; n8++) {
        const int col = n8 * 8 + ((lane & 3) << 1);
        float v0 = oacc[n8][0] * i0, v1 = oacc[n8][1] * i0;
        float v2 = oacc[n8][2] * i1, v3 = oacc[n8][3] * i1;
        uint32_t h0 = cvt2(v1, v0), h1 = cvt2(v3, v2);
        *(uint32_t*)(g_aohi + base0 + col) = h0;
        *(uint32_t*)(g_aolo + base0 + col) = losplit(h0, v1, v0);
        *(uint32_t*)(g_aohi + base1 + col) = h1;
        *(uint32_t*)(g_aolo + base1 + col) = losplit(h1, v3, v2);
    }
}

// ---------------------------------------------------------------------------
extern "C" void kernel_launch(void* const* d_in, const int* in_sizes, int n_in,
                              void* d_out, int out_size)
{
    (void)in_sizes; (void)n_in; (void)out_size;
    const float* x      = (const float*)d_in[0];
    const uint8_t* mask = (const uint8_t*)d_in[1];
    const float* Wqkv   = (const float*)d_in[2];
    const float* bqkv   = (const float*)d_in[3];
    const float* Wproj  = (const float*)d_in[4];
    const float* bproj  = (const float*)d_in[5];
    float* out = (float*)d_out;

    bf *xhi, *xlo, *aohi, *aolo, *wqh, *wql, *wph, *wpl;
    cudaGetSymbolAddress((void**)&xhi, g_xhi);
    cudaGetSymbolAddress((void**)&xlo, g_xlo);
    cudaGetSymbolAddress((void**)&aohi, g_aohi);
    cudaGetSymbolAddress((void**)&aolo, g_aolo);
    cudaGetSymbolAddress((void**)&wqh, g_wqt_hi);
    cudaGetSymbolAddress((void**)&wql, g_wqt_lo);
    cudaGetSymbolAddress((void**)&wph, g_wpt_hi);
    cudaGetSymbolAddress((void**)&wpl, g_wpt_lo);

    const int NE = Bb * Nn * Cc;
    split_bf16<<<NE / 4 / 256, 256>>>((const float4*)x, xhi, xlo);
    transpose_split<<<dim3(3 * Cc / 32, Cc / 32), dim3(32, 8)>>>(Wqkv, wqh, wql, Cc, 3 * Cc);
    transpose_split<<<dim3(Cc / 32, Cc / 32), dim3(32, 8)>>>(Wproj, wph, wpl, Cc, Cc);

    cudaFuncSetAttribute(mma_gemm<0>, cudaFuncAttributeMaxDynamicSharedMemorySize, GEMM_SMEM);
    mma_gemm<0><<<dim3(3 * Cc / 128, Bb * Nn / 128), 256, GEMM_SMEM>>>(
        xhi, xlo, wqh, wql, bqkv, nullptr, 3 * Cc);

    cudaFuncSetAttribute(attn_mma, cudaFuncAttributeMaxDynamicSharedMemorySize, ATTN_SMEM);
    attn_mma<<<dim3(Nn / 128, Hh, Bb), 256, ATTN_SMEM>>>(mask);

    cudaFuncSetAttribute(mma_gemm<1>, cudaFuncAttributeMaxDynamicSharedMemorySize, GEMM_SMEM);
    mma_gemm<1><<<dim3(Cc / 128, Bb * Nn / 128), 256, GEMM_SMEM>>>(
        aohi, aolo, wph, wpl, bproj, out, Cc);
}